// round 7
// baseline (speedup 1.0000x reference)
#include <cuda_runtime.h>
#include <cstdint>

#define BATCH 4
#define SEQ   4096
#define CDIM  256
#define DDIM  32
#define TQ    128
#define TK    64
#define NT_TILES (SEQ / TK)
#define NTHR  512

// ---- scratch ----
__device__ float g_q[BATCH * SEQ * DDIM];
__device__ float g_k[BATCH * SEQ * DDIM];
__device__ float g_v[BATCH * SEQ * CDIM];

// ---- helpers ----
__device__ __forceinline__ unsigned long long pack2(float lo, float hi) {
    unsigned long long r;
    asm("mov.b64 %0, {%1, %2};" : "=l"(r) : "f"(lo), "f"(hi));
    return r;
}
__device__ __forceinline__ void unpack2(unsigned long long v, float& lo, float& hi) {
    asm("mov.b64 {%0, %1}, %2;" : "=f"(lo), "=f"(hi) : "l"(v));
}
__device__ __forceinline__ unsigned long long ffma2(unsigned long long a, unsigned long long b,
                                                    unsigned long long c) {
    unsigned long long d;
    asm("fma.rn.f32x2 %0, %1, %2, %3;" : "=l"(d) : "l"(a), "l"(b), "l"(c));
    return d;
}
__device__ __forceinline__ uint32_t smem_u32(const void* p) {
    uint32_t a;
    asm("{ .reg .u64 t; cvta.to.shared.u64 t, %1; cvt.u32.u64 %0, t; }" : "=r"(a) : "l"(p));
    return a;
}
__device__ __forceinline__ void cp_async16(uint32_t dst, const void* src) {
    asm volatile("cp.async.cg.shared.global [%0], [%1], 16;" :: "r"(dst), "l"(src));
}
__device__ __forceinline__ uint32_t to_tf32(float f) {
    uint32_t u;
    asm("cvt.rna.tf32.f32 %0, %1;" : "=r"(u) : "f"(f));
    return u;
}
__device__ __forceinline__ float trunc13(float x) {
    return __uint_as_float(__float_as_uint(x) & 0xFFFFE000u);
}
__device__ __forceinline__ void mma8(float d[4], uint32_t a0, uint32_t a1, uint32_t a2,
                                     uint32_t a3, uint32_t b0, uint32_t b1) {
    asm volatile(
        "mma.sync.aligned.m16n8k8.row.col.f32.tf32.tf32.f32 "
        "{%0,%1,%2,%3}, {%4,%5,%6,%7}, {%8,%9}, {%0,%1,%2,%3};"
        : "+f"(d[0]), "+f"(d[1]), "+f"(d[2]), "+f"(d[3])
        : "r"(a0), "r"(a1), "r"(a2), "r"(a3), "r"(b0), "r"(b1));
}

// ---- smem byte offsets (round-5 layouts, proven) ----
#define OFF_QHI 0
#define OFF_QLO 16384
#define OFF_KTH 32768
#define OFF_KTL 40960
#define OFF_P   49152
#define OFF_V   81920       /* 2 x 65536 */
#define OFF_L   212992
#define OFF_LP  213504      /* 8 x 128 floats */
#define FLASH_SMEM 217600

// round-5 word-index swizzles (proven conflict behavior)
__device__ __forceinline__ int pQ(int r, int d)  { return r * 32 + (d ^ ((r & 7) * 4)); }
__device__ __forceinline__ int pKT(int d, int k) { return d * 64 + (k ^ ((d & 3) * 8)); }
__device__ __forceinline__ int pP(int r, int c)  { return r * 64 + (c ^ ((r & 7) * 4)); }
__device__ __forceinline__ int pV(int k, int n)  { return k * 256 + (n ^ ((k & 3) * 8)); }

// ============================================================================
// Flash attention on mma.sync tf32, 512 threads = 16 warps (4/SMSP).
// mw = wid&1 (64 rows each), nw = wid>>1 in 0..7 (8 keys / 32 PV cols each)
// ============================================================================
__global__ __launch_bounds__(NTHR, 1)
void flash_mma(const float* __restrict__ Qg, const float* __restrict__ Kg,
               const float* __restrict__ Vg, const float* __restrict__ X,
               float* __restrict__ Out) {
    extern __shared__ char smem[];
    float*    sQh  = (float*)(smem + OFF_QHI);
    float*    sQl  = (float*)(smem + OFF_QLO);
    float*    sKTh = (float*)(smem + OFF_KTH);
    float*    sKTl = (float*)(smem + OFF_KTL);
    uint32_t* sPu  = (uint32_t*)(smem + OFF_P);
    uint32_t* sVu  = (uint32_t*)(smem + OFF_V);
    float*    sL   = (float*)(smem + OFF_L);
    float*    sLp  = (float*)(smem + OFF_LP);
    const uint32_t sb = smem_u32(smem);

    const int tid  = threadIdx.x;
    const int lane = tid & 31;
    const int wid  = tid >> 5;
    const int mw   = wid & 1;
    const int nw   = wid >> 1;         // 0..7
    const int g    = lane >> 2;
    const int l4   = lane & 3;
    const int b    = blockIdx.y;
    const int q0   = blockIdx.x * TQ;

    const float* Qb = Qg + ((size_t)b * SEQ + q0) * DDIM;
    const float* Kb = Kg + (size_t)b * SEQ * DDIM;
    const float* Vb = Vg + (size_t)b * SEQ * CDIM;

    // ---- prologue ----
    if (tid < 128) sL[tid] = 0.0f;
    // Q hi/lo split
#pragma unroll
    for (int i = 0; i < 2; i++) {
        int idx = tid + i * NTHR;
        int r = idx >> 3, d4 = idx & 7;
        float4 v = *(const float4*)(Qb + r * DDIM + d4 * 4);
        float4 hi, lo;
        hi.x = trunc13(v.x); lo.x = __uint_as_float(to_tf32(v.x - hi.x));
        hi.y = trunc13(v.y); lo.y = __uint_as_float(to_tf32(v.y - hi.y));
        hi.z = trunc13(v.z); lo.z = __uint_as_float(to_tf32(v.z - hi.z));
        hi.w = trunc13(v.w); lo.w = __uint_as_float(to_tf32(v.w - hi.w));
        int base = r * 32 + ((d4 * 4) ^ ((r & 7) * 4));
        *(float4*)(sQh + base) = hi;
        *(float4*)(sQl + base) = lo;
    }
    // K(0) -> KT smem
    {
        int key = tid >> 3, d4 = tid & 7;
        float4 v = *(const float4*)(Kb + key * DDIM + d4 * 4);
        float hv[4] = {trunc13(v.x), trunc13(v.y), trunc13(v.z), trunc13(v.w)};
        float lv[4] = {v.x - hv[0], v.y - hv[1], v.z - hv[2], v.w - hv[3]};
#pragma unroll
        for (int j = 0; j < 4; j++) {
            int d = d4 * 4 + j;
            sKTh[pKT(d, key)] = hv[j];
            sKTl[pKT(d, key)] = __uint_as_float(to_tf32(lv[j]));
        }
    }
    // V(0) cp.async
#pragma unroll
    for (int i = 0; i < 8; i++) {
        int f = tid + i * NTHR;
        int key = f >> 6, n4 = f & 63;
        uint32_t dst = sb + OFF_V + (uint32_t)pV(key, n4 * 4) * 4u;
        cp_async16(dst, Vb + (size_t)key * CDIM + n4 * 4);
    }
    asm volatile("cp.async.commit_group;" ::: "memory");
    __syncthreads();

    float oa[4][4][4];
#pragma unroll
    for (int mt = 0; mt < 4; mt++)
#pragma unroll
        for (int nt = 0; nt < 4; nt++)
#pragma unroll
            for (int c = 0; c < 4; c++) oa[mt][nt][c] = 0.0f;

#pragma unroll 1
    for (int t = 0; t < NT_TILES; t++) {
        const int buf = t & 1;
        const bool have_next = (t + 1 < NT_TILES);

        // 1. V(t) ready
        asm volatile("cp.async.wait_group 0;" ::: "memory");

        // 2. prefetch V(t+1)
        if (have_next) {
            const float* Vs = Vb + (size_t)(t + 1) * TK * CDIM;
            uint32_t vb0 = sb + OFF_V + (uint32_t)(1 - buf) * 65536u;
#pragma unroll
            for (int i = 0; i < 8; i++) {
                int f = tid + i * NTHR;
                int key = f >> 6, n4 = f & 63;
                cp_async16(vb0 + (uint32_t)pV(key, n4 * 4) * 4u, Vs + (size_t)key * CDIM + n4 * 4);
            }
            asm volatile("cp.async.commit_group;" ::: "memory");
        }
        // 3. stage K(t+1)
        float4 kreg;
        if (have_next) {
            const float* Ks = Kb + (size_t)(t + 1) * TK * DDIM;
            kreg = *(const float4*)(Ks + (tid >> 3) * DDIM + (tid & 7) * 4);
        }

        // 4. S = QK^T (compensated tf32): each warp 64 rows x 8 keys
        float sa[4][4];
#pragma unroll
        for (int mt = 0; mt < 4; mt++)
#pragma unroll
            for (int c = 0; c < 4; c++) sa[mt][c] = 0.0f;

#pragma unroll
        for (int ks = 0; ks < 4; ks++) {
            const int k0 = ks * 8;
            const int key = nw * 8 + g;
            int i0 = pKT(k0 + l4, key), i1 = pKT(k0 + 4 + l4, key);
            uint32_t bh0 = __float_as_uint(sKTh[i0]);
            uint32_t bh1 = __float_as_uint(sKTh[i1]);
            uint32_t bl0 = __float_as_uint(sKTl[i0]);
            uint32_t bl1 = __float_as_uint(sKTl[i1]);
#pragma unroll
            for (int mt = 0; mt < 4; mt++) {
                int r0 = mw * 64 + mt * 16 + g;
                uint32_t ah0 = __float_as_uint(sQh[pQ(r0, k0 + l4)]);
                uint32_t ah1 = __float_as_uint(sQh[pQ(r0 + 8, k0 + l4)]);
                uint32_t ah2 = __float_as_uint(sQh[pQ(r0, k0 + 4 + l4)]);
                uint32_t ah3 = __float_as_uint(sQh[pQ(r0 + 8, k0 + 4 + l4)]);
                uint32_t al0 = __float_as_uint(sQl[pQ(r0, k0 + l4)]);
                uint32_t al1 = __float_as_uint(sQl[pQ(r0 + 8, k0 + l4)]);
                uint32_t al2 = __float_as_uint(sQl[pQ(r0, k0 + 4 + l4)]);
                uint32_t al3 = __float_as_uint(sQl[pQ(r0 + 8, k0 + 4 + l4)]);
                mma8(sa[mt], ah0, ah1, ah2, ah3, bh0, bh1);
                mma8(sa[mt], ah0, ah1, ah2, ah3, bl0, bl1);
                mma8(sa[mt], al0, al1, al2, al3, bh0, bh1);
            }
        }

        // 5. exp (no max), P -> smem (tf32), partial row sums
#pragma unroll
        for (int mt = 0; mt < 4; mt++) {
            int r0 = mw * 64 + mt * 16 + g;
            int col = nw * 8 + l4 * 2;
            uint32_t e0 = to_tf32(__expf(sa[mt][0]));
            uint32_t e1 = to_tf32(__expf(sa[mt][1]));
            uint32_t e2 = to_tf32(__expf(sa[mt][2]));
            uint32_t e3 = to_tf32(__expf(sa[mt][3]));
            float s0 = __uint_as_float(e0) + __uint_as_float(e1);
            float s1 = __uint_as_float(e2) + __uint_as_float(e3);
            sPu[pP(r0, col)]     = e0;
            sPu[pP(r0, col + 1)] = e1;
            sPu[pP(r0 + 8, col)]     = e2;
            sPu[pP(r0 + 8, col + 1)] = e3;
            s0 += __shfl_xor_sync(0xffffffffu, s0, 1);
            s0 += __shfl_xor_sync(0xffffffffu, s0, 2);
            s1 += __shfl_xor_sync(0xffffffffu, s1, 1);
            s1 += __shfl_xor_sync(0xffffffffu, s1, 2);
            if (l4 == 0) {
                sLp[nw * 128 + r0] = s0;
                sLp[nw * 128 + r0 + 8] = s1;
            }
        }
        __syncthreads();   // sync1: sP/sLp visible, KT free, V(t) visible

        // 6. KT(t+1) store + l accumulate
        if (have_next) {
            int key = tid >> 3, d4 = tid & 7;
            float4 v = kreg;
            float hv[4] = {trunc13(v.x), trunc13(v.y), trunc13(v.z), trunc13(v.w)};
            float lv[4] = {v.x - hv[0], v.y - hv[1], v.z - hv[2], v.w - hv[3]};
#pragma unroll
            for (int j = 0; j < 4; j++) {
                int d = d4 * 4 + j;
                sKTh[pKT(d, key)] = hv[j];
                sKTl[pKT(d, key)] = __uint_as_float(to_tf32(lv[j]));
            }
        }
        if (tid < 128) {
            float acc = 0.0f;
#pragma unroll
            for (int j = 0; j < 8; j++) acc += sLp[j * 128 + tid];
            sL[tid] += acc;
        }

        // 7. O += P @ V : each warp 64 rows x 32 cols
        const uint32_t* sVb = sVu + (size_t)buf * 16384;
#pragma unroll
        for (int ks = 0; ks < 8; ks++) {
            const int k0 = ks * 8;
            uint32_t pa[4][4];
#pragma unroll
            for (int mt = 0; mt < 4; mt++) {
                int r0 = mw * 64 + mt * 16 + g;
                pa[mt][0] = sPu[pP(r0, k0 + l4)];
                pa[mt][1] = sPu[pP(r0 + 8, k0 + l4)];
                pa[mt][2] = sPu[pP(r0, k0 + 4 + l4)];
                pa[mt][3] = sPu[pP(r0 + 8, k0 + 4 + l4)];
            }
#pragma unroll
            for (int nt = 0; nt < 4; nt++) {
                int n = nw * 32 + nt * 8 + g;
                uint32_t b0 = sVb[pV(k0 + l4, n)];
                uint32_t b1 = sVb[pV(k0 + 4 + l4, n)];
#pragma unroll
                for (int mt = 0; mt < 4; mt++)
                    mma8(oa[mt][nt], pa[mt][0], pa[mt][1], pa[mt][2], pa[mt][3], b0, b1);
            }
        }
        __syncthreads();   // sync2
    }

    // ---- epilogue: O/l + residual ----
#pragma unroll
    for (int mt = 0; mt < 4; mt++) {
        int r0 = mw * 64 + mt * 16 + g;
        float inv0 = 1.0f / sL[r0];
        float inv1 = 1.0f / sL[r0 + 8];
        size_t row0 = (size_t)b * SEQ + q0 + r0;
#pragma unroll
        for (int nt = 0; nt < 4; nt++) {
            int col = nw * 32 + nt * 8 + l4 * 2;
            const float2* x0 = (const float2*)(X + (row0)*CDIM + col);
            const float2* x1 = (const float2*)(X + (row0 + 8) * CDIM + col);
            float2 xv0 = *x0, xv1 = *x1;
            float2 o0, o1;
            o0.x = oa[mt][nt][0] * inv0 + xv0.x;
            o0.y = oa[mt][nt][1] * inv0 + xv0.y;
            o1.x = oa[mt][nt][2] * inv1 + xv1.x;
            o1.y = oa[mt][nt][3] * inv1 + xv1.y;
            *(float2*)(Out + (row0)*CDIM + col) = o0;
            *(float2*)(Out + (row0 + 8) * CDIM + col) = o1;
        }
    }
}

// ============================================================================
// Merged q+k projection (round-6, benched 33 µs)
// ============================================================================
__global__ __launch_bounds__(128)
void sgemm_qk(const float* __restrict__ A,
              const float* __restrict__ Wq, const float* __restrict__ bq,
              const float* __restrict__ Wk, const float* __restrict__ bk,
              float* __restrict__ Yq, float* __restrict__ Yk) {
    constexpr int BM = 64, BK = 16, BN = 32, TM = 4, TN = 4, TX = 8, NT = 128;
    __shared__ float As[BK][BM + 4];
    __shared__ float Bq[BK][BN];
    __shared__ float Bk[BK][BN];
    const int tid = threadIdx.x;
    const int tx = tid % TX, ty = tid / TX;
    const int m0 = blockIdx.x * BM;

    unsigned long long aq[TM][2], ak[TM][2];
#pragma unroll
    for (int i = 0; i < TM; i++) {
        aq[i][0] = aq[i][1] = 0ull;
        ak[i][0] = ak[i][1] = 0ull;
    }

    for (int k0 = 0; k0 < CDIM; k0 += BK) {
        for (int idx = tid; idx < BM * BK / 4; idx += NT) {
            int m = idx / (BK / 4), kq = idx % (BK / 4);
            float4 t4 = *(const float4*)(A + (size_t)(m0 + m) * CDIM + k0 + kq * 4);
            As[kq * 4 + 0][m] = t4.x; As[kq * 4 + 1][m] = t4.y;
            As[kq * 4 + 2][m] = t4.z; As[kq * 4 + 3][m] = t4.w;
        }
        for (int idx = tid; idx < BK * BN / 4; idx += NT) {
            int kk = idx / (BN / 4), nq = idx % (BN / 4);
            *(float4*)&Bq[kk][nq * 4] = *(const float4*)(Wq + (size_t)(k0 + kk) * DDIM + nq * 4);
            *(float4*)&Bk[kk][nq * 4] = *(const float4*)(Wk + (size_t)(k0 + kk) * DDIM + nq * 4);
        }
        __syncthreads();
#pragma unroll
        for (int kk = 0; kk < BK; kk++) {
            ulonglong2 bbq = *(const ulonglong2*)&Bq[kk][tx * TN];
            ulonglong2 bbk = *(const ulonglong2*)&Bk[kk][tx * TN];
#pragma unroll
            for (int i = 0; i < TM; i++) {
                float a = As[kk][ty * TM + i];
                unsigned long long a2 = pack2(a, a);
                aq[i][0] = ffma2(bbq.x, a2, aq[i][0]);
                aq[i][1] = ffma2(bbq.y, a2, aq[i][1]);
                ak[i][0] = ffma2(bbk.x, a2, ak[i][0]);
                ak[i][1] = ffma2(bbk.y, a2, ak[i][1]);
            }
        }
        __syncthreads();
    }
    float4 bq4 = *(const float4*)(bq + tx * TN);
    float4 bk4 = *(const float4*)(bk + tx * TN);
#pragma unroll
    for (int i = 0; i < TM; i++) {
        int m = m0 + ty * TM + i;
        float v0, v1, v2, v3;
        unpack2(aq[i][0], v0, v1);
        unpack2(aq[i][1], v2, v3);
        float4 o;
        o.x = v0 + bq4.x; o.y = v1 + bq4.y; o.z = v2 + bq4.z; o.w = v3 + bq4.w;
        *(float4*)(Yq + (size_t)m * DDIM + tx * TN) = o;
        unpack2(ak[i][0], v0, v1);
        unpack2(ak[i][1], v2, v3);
        o.x = v0 + bk4.x; o.y = v1 + bk4.y; o.z = v2 + bk4.z; o.w = v3 + bk4.w;
        *(float4*)(Yk + (size_t)m * DDIM + tx * TN) = o;
    }
}

// ============================================================================
// V projection GEMM (round-2, passing)
// ============================================================================
template<int BM, int BN, int BK, int TM, int TN>
__global__ void sgemm_bias_kernel(const float* __restrict__ A, const float* __restrict__ W,
                                  const float* __restrict__ bias, float* __restrict__ Y,
                                  int M, int Kd, int N) {
    __shared__ float As[BK][BM + 4];
    __shared__ float Bs[BK][BN];
    constexpr int TX = BN / TN;
    constexpr int NT = (BM / TM) * TX;
    const int tid = threadIdx.x;
    const int tx = tid % TX, ty = tid / TX;
    const int m0 = blockIdx.x * BM, n0 = blockIdx.y * BN;

    unsigned long long acc[TM][2];
#pragma unroll
    for (int i = 0; i < TM; i++) { acc[i][0] = 0ull; acc[i][1] = 0ull; }

    for (int k0 = 0; k0 < Kd; k0 += BK) {
        for (int idx = tid; idx < BM * BK / 4; idx += NT) {
            int m = idx / (BK / 4), kq = idx % (BK / 4);
            float4 t4 = *(const float4*)(A + (size_t)(m0 + m) * Kd + k0 + kq * 4);
            As[kq * 4 + 0][m] = t4.x; As[kq * 4 + 1][m] = t4.y;
            As[kq * 4 + 2][m] = t4.z; As[kq * 4 + 3][m] = t4.w;
        }
        for (int idx = tid; idx < BK * BN / 4; idx += NT) {
            int kk = idx / (BN / 4), nq = idx % (BN / 4);
            *(float4*)&Bs[kk][nq * 4] = *(const float4*)(W + (size_t)(k0 + kk) * N + n0 + nq * 4);
        }
        __syncthreads();
#pragma unroll
        for (int kk = 0; kk < BK; kk++) {
            ulonglong2 bb = *(const ulonglong2*)&Bs[kk][tx * TN];
#pragma unroll
            for (int i = 0; i < TM; i++) {
                float a = As[kk][ty * TM + i];
                unsigned long long a2 = pack2(a, a);
                acc[i][0] = ffma2(bb.x, a2, acc[i][0]);
                acc[i][1] = ffma2(bb.y, a2, acc[i][1]);
            }
        }
        __syncthreads();
    }
    float4 bv4 = *(const float4*)(bias + n0 + tx * TN);
#pragma unroll
    for (int i = 0; i < TM; i++) {
        int m = m0 + ty * TM + i;
        float v0, v1, v2, v3;
        unpack2(acc[i][0], v0, v1);
        unpack2(acc[i][1], v2, v3);
        float4 o;
        o.x = v0 + bv4.x; o.y = v1 + bv4.y; o.z = v2 + bv4.z; o.w = v3 + bv4.w;
        *(float4*)(Y + (size_t)m * N + n0 + tx * TN) = o;
    }
}

// ============================================================================
extern "C" void kernel_launch(void* const* d_in, const int* in_sizes, int n_in,
                              void* d_out, int out_size) {
    const float* x  = (const float*)d_in[0];
    const float* wq = (const float*)d_in[1];
    const float* bq = (const float*)d_in[2];
    const float* wk = (const float*)d_in[3];
    const float* bk = (const float*)d_in[4];
    const float* wv = (const float*)d_in[5];
    const float* bv = (const float*)d_in[6];
    float* out = (float*)d_out;

    float *qp, *kp, *vp;
    cudaGetSymbolAddress((void**)&qp, g_q);
    cudaGetSymbolAddress((void**)&kp, g_k);
    cudaGetSymbolAddress((void**)&vp, g_v);

    {
        dim3 g(BATCH * SEQ / 64, 1);
        sgemm_qk<<<g, 128>>>(x, wq, bq, wk, bk, qp, kp);
    }
    {
        dim3 g(BATCH * SEQ / 128, CDIM / 64);
        sgemm_bias_kernel<128, 64, 16, 8, 4><<<g, 256>>>(x, wv, bv, vp, BATCH * SEQ, CDIM, CDIM);
    }
    {
        cudaFuncSetAttribute(flash_mma, cudaFuncAttributeMaxDynamicSharedMemorySize, FLASH_SMEM);
        dim3 g(SEQ / TQ, BATCH);
        flash_mma<<<g, NTHR, FLASH_SMEM>>>(qp, kp, vp, x, out);
    }
}

// round 8
// speedup vs baseline: 1.0795x; 1.0795x over previous
#include <cuda_runtime.h>
#include <cstdint>

#define BATCH 4
#define SEQ   4096
#define CDIM  256
#define DDIM  32
#define TQ    128
#define TK    64
#define NT_TILES (SEQ / TK)

// ---- scratch ----
__device__ float g_q[BATCH * SEQ * DDIM];
__device__ float g_k[BATCH * SEQ * DDIM];
__device__ float g_v[BATCH * SEQ * CDIM];

// ---- helpers ----
__device__ __forceinline__ unsigned long long pack2(float lo, float hi) {
    unsigned long long r;
    asm("mov.b64 %0, {%1, %2};" : "=l"(r) : "f"(lo), "f"(hi));
    return r;
}
__device__ __forceinline__ void unpack2(unsigned long long v, float& lo, float& hi) {
    asm("mov.b64 {%0, %1}, %2;" : "=f"(lo), "=f"(hi) : "l"(v));
}
__device__ __forceinline__ unsigned long long ffma2(unsigned long long a, unsigned long long b,
                                                    unsigned long long c) {
    unsigned long long d;
    asm("fma.rn.f32x2 %0, %1, %2, %3;" : "=l"(d) : "l"(a), "l"(b), "l"(c));
    return d;
}
__device__ __forceinline__ uint32_t smem_u32(const void* p) {
    uint32_t a;
    asm("{ .reg .u64 t; cvta.to.shared.u64 t, %1; cvt.u32.u64 %0, t; }" : "=r"(a) : "l"(p));
    return a;
}
__device__ __forceinline__ void cp_async16(uint32_t dst, const void* src) {
    asm volatile("cp.async.cg.shared.global [%0], [%1], 16;" :: "r"(dst), "l"(src));
}
__device__ __forceinline__ uint32_t to_tf32(float f) {
    uint32_t u;
    asm("cvt.rna.tf32.f32 %0, %1;" : "=r"(u) : "f"(f));
    return u;
}
__device__ __forceinline__ float trunc13(float x) {
    return __uint_as_float(__float_as_uint(x) & 0xFFFFE000u);
}
__device__ __forceinline__ void mma8(float d[4], uint32_t a0, uint32_t a1, uint32_t a2,
                                     uint32_t a3, uint32_t b0, uint32_t b1) {
    asm volatile(
        "mma.sync.aligned.m16n8k8.row.col.f32.tf32.tf32.f32 "
        "{%0,%1,%2,%3}, {%4,%5,%6,%7}, {%8,%9}, {%0,%1,%2,%3};"
        : "+f"(d[0]), "+f"(d[1]), "+f"(d[2]), "+f"(d[3])
        : "r"(a0), "r"(a1), "r"(a2), "r"(a3), "r"(b0), "r"(b1));
}

// ---- smem byte offsets ----
#define OFF_QHI 0                 /* 16 KB */
#define OFF_QLO 16384             /* 16 KB */
#define OFF_KTH 32768             /* 2 x 8 KB (double-buffered) */
#define OFF_KTL 49152             /* 2 x 8 KB */
#define OFF_P   65536             /* 32 KB */
#define OFF_V   98304             /* 2 x 64 KB */
#define OFF_L   229376            /* 512 B */
#define OFF_LP  229888            /* 2 KB */
#define FLASH_SMEM 231936

// round-5 word-index swizzles (proven)
__device__ __forceinline__ int pQ(int r, int d)  { return r * 32 + (d ^ ((r & 7) * 4)); }
__device__ __forceinline__ int pKT(int d, int k) { return d * 64 + (k ^ ((d & 3) * 8)); }
__device__ __forceinline__ int pP(int r, int c)  { return r * 64 + (c ^ ((r & 7) * 4)); }
__device__ __forceinline__ int pV(int k, int n)  { return k * 256 + (n ^ ((k & 3) * 8)); }

// ============================================================================
// Flash attention, mma.sync tf32, fused cross-tile MMA phases.
// 256 threads = 8 warps: mw = wid&1 (64 rows), nw = wid>>1 (16 keys / 64 PV cols)
// ============================================================================
__global__ __launch_bounds__(256, 1)
void flash_mma(const float* __restrict__ Qg, const float* __restrict__ Kg,
               const float* __restrict__ Vg, const float* __restrict__ X,
               float* __restrict__ Out) {
    extern __shared__ char smem[];
    float*    sQh  = (float*)(smem + OFF_QHI);
    float*    sQl  = (float*)(smem + OFF_QLO);
    uint32_t* sPu  = (uint32_t*)(smem + OFF_P);
    uint32_t* sVu  = (uint32_t*)(smem + OFF_V);
    float*    sL   = (float*)(smem + OFF_L);
    float*    sLp  = (float*)(smem + OFF_LP);
    const uint32_t sb = smem_u32(smem);

    const int tid  = threadIdx.x;
    const int lane = tid & 31;
    const int wid  = tid >> 5;
    const int mw   = wid & 1;
    const int nw   = wid >> 1;
    const int g    = lane >> 2;
    const int l4   = lane & 3;
    const int b    = blockIdx.y;
    const int q0   = blockIdx.x * TQ;

    const float* Qb = Qg + ((size_t)b * SEQ + q0) * DDIM;
    const float* Kb = Kg + (size_t)b * SEQ * DDIM;
    const float* Vb = Vg + (size_t)b * SEQ * CDIM;

    // ---- prologue ----
    if (tid < 128) sL[tid] = 0.0f;
    // Q hi/lo split
#pragma unroll
    for (int i = 0; i < 4; i++) {
        int idx = tid + i * 256;
        int r = idx >> 3, d4 = idx & 7;
        float4 v = *(const float4*)(Qb + r * DDIM + d4 * 4);
        float4 hi, lo;
        hi.x = trunc13(v.x); lo.x = __uint_as_float(to_tf32(v.x - hi.x));
        hi.y = trunc13(v.y); lo.y = __uint_as_float(to_tf32(v.y - hi.y));
        hi.z = trunc13(v.z); lo.z = __uint_as_float(to_tf32(v.z - hi.z));
        hi.w = trunc13(v.w); lo.w = __uint_as_float(to_tf32(v.w - hi.w));
        int base = r * 32 + ((d4 * 4) ^ ((r & 7) * 4));
        *(float4*)(sQh + base) = hi;
        *(float4*)(sQl + base) = lo;
    }
    // K(0) -> KT buffer 0
    {
        float* sKTh0 = (float*)(smem + OFF_KTH);
        float* sKTl0 = (float*)(smem + OFF_KTL);
#pragma unroll
        for (int i = 0; i < 2; i++) {
            int idx = tid + i * 256;
            int key = idx >> 3, d4 = idx & 7;
            float4 v = *(const float4*)(Kb + key * DDIM + d4 * 4);
            float hv[4] = {trunc13(v.x), trunc13(v.y), trunc13(v.z), trunc13(v.w)};
            float lv[4] = {v.x - hv[0], v.y - hv[1], v.z - hv[2], v.w - hv[3]};
#pragma unroll
            for (int j = 0; j < 4; j++) {
                int d = d4 * 4 + j;
                sKTh0[pKT(d, key)] = hv[j];
                sKTl0[pKT(d, key)] = __uint_as_float(to_tf32(lv[j]));
            }
        }
    }
    // V(0) cp.async
#pragma unroll
    for (int i = 0; i < 16; i++) {
        int f = tid + i * 256;
        int key = f >> 6, n4 = f & 63;
        uint32_t dst = sb + OFF_V + (uint32_t)pV(key, n4 * 4) * 4u;
        cp_async16(dst, Vb + (size_t)key * CDIM + n4 * 4);
    }
    asm volatile("cp.async.commit_group;" ::: "memory");
    __syncthreads();

    float oa[4][8][4];
#pragma unroll
    for (int mt = 0; mt < 4; mt++)
#pragma unroll
        for (int nt = 0; nt < 8; nt++)
#pragma unroll
            for (int c = 0; c < 4; c++) oa[mt][nt][c] = 0.0f;

    float sa[4][2][4];
#pragma unroll
    for (int mt = 0; mt < 4; mt++)
#pragma unroll
        for (int nt = 0; nt < 2; nt++)
#pragma unroll
            for (int c = 0; c < 4; c++) sa[mt][nt][c] = 0.0f;

    // ---- QK(0) (KT buffer 0) ----
    {
        const float* sKTh = (const float*)(smem + OFF_KTH);
        const float* sKTl = (const float*)(smem + OFF_KTL);
#pragma unroll
        for (int ks = 0; ks < 4; ks++) {
            const int k0 = ks * 8;
            uint32_t bh[2][2], bl[2][2];
#pragma unroll
            for (int nt = 0; nt < 2; nt++) {
                int key = nw * 16 + nt * 8 + g;
                int i0 = pKT(k0 + l4, key), i1 = pKT(k0 + 4 + l4, key);
                bh[nt][0] = __float_as_uint(sKTh[i0]);
                bh[nt][1] = __float_as_uint(sKTh[i1]);
                bl[nt][0] = __float_as_uint(sKTl[i0]);
                bl[nt][1] = __float_as_uint(sKTl[i1]);
            }
#pragma unroll
            for (int mt = 0; mt < 4; mt++) {
                int r0 = mw * 64 + mt * 16 + g;
                uint32_t ah0 = __float_as_uint(sQh[pQ(r0, k0 + l4)]);
                uint32_t ah1 = __float_as_uint(sQh[pQ(r0 + 8, k0 + l4)]);
                uint32_t ah2 = __float_as_uint(sQh[pQ(r0, k0 + 4 + l4)]);
                uint32_t ah3 = __float_as_uint(sQh[pQ(r0 + 8, k0 + 4 + l4)]);
                uint32_t al0 = __float_as_uint(sQl[pQ(r0, k0 + l4)]);
                uint32_t al1 = __float_as_uint(sQl[pQ(r0 + 8, k0 + l4)]);
                uint32_t al2 = __float_as_uint(sQl[pQ(r0, k0 + 4 + l4)]);
                uint32_t al3 = __float_as_uint(sQl[pQ(r0 + 8, k0 + 4 + l4)]);
#pragma unroll
                for (int nt = 0; nt < 2; nt++) {
                    mma8(sa[mt][nt], ah0, ah1, ah2, ah3, bh[nt][0], bh[nt][1]);
                    mma8(sa[mt][nt], ah0, ah1, ah2, ah3, bl[nt][0], bl[nt][1]);
                    mma8(sa[mt][nt], al0, al1, al2, al3, bh[nt][0], bh[nt][1]);
                }
            }
        }
    }

#pragma unroll 1
    for (int t = 0; t < NT_TILES; t++) {
        const int buf = t & 1;
        const int nbuf = 1 - buf;
        const bool have_next = (t + 1 < NT_TILES);

        // A0. stage K(t+1) from gmem
        float4 kreg[2];
        if (have_next) {
            const float* Ks = Kb + (size_t)(t + 1) * TK * DDIM;
#pragma unroll
            for (int i = 0; i < 2; i++) {
                int idx = tid + i * 256;
                kreg[i] = *(const float4*)(Ks + (idx >> 3) * DDIM + (idx & 7) * 4);
            }
        }

        // A1. exp (no max), P(t) -> smem, partial row sums
#pragma unroll
        for (int mt = 0; mt < 4; mt++) {
            int r0 = mw * 64 + mt * 16 + g;
            float s0 = 0.0f, s1 = 0.0f;
#pragma unroll
            for (int nt = 0; nt < 2; nt++) {
                int col = nw * 16 + nt * 8 + l4 * 2;
                uint32_t e0 = to_tf32(__expf(sa[mt][nt][0]));
                uint32_t e1 = to_tf32(__expf(sa[mt][nt][1]));
                uint32_t e2 = to_tf32(__expf(sa[mt][nt][2]));
                uint32_t e3 = to_tf32(__expf(sa[mt][nt][3]));
                s0 += __uint_as_float(e0) + __uint_as_float(e1);
                s1 += __uint_as_float(e2) + __uint_as_float(e3);
                sPu[pP(r0, col)]     = e0;
                sPu[pP(r0, col + 1)] = e1;
                sPu[pP(r0 + 8, col)]     = e2;
                sPu[pP(r0 + 8, col + 1)] = e3;
            }
            s0 += __shfl_xor_sync(0xffffffffu, s0, 1);
            s0 += __shfl_xor_sync(0xffffffffu, s0, 2);
            s1 += __shfl_xor_sync(0xffffffffu, s1, 1);
            s1 += __shfl_xor_sync(0xffffffffu, s1, 2);
            if (l4 == 0) {
                sLp[nw * 128 + r0] = s0;
                sLp[nw * 128 + r0 + 8] = s1;
            }
        }

        // A2. KT(t+1) -> buffer nbuf
        if (have_next) {
            float* sKThN = (float*)(smem + OFF_KTH + nbuf * 8192);
            float* sKTlN = (float*)(smem + OFF_KTL + nbuf * 8192);
#pragma unroll
            for (int i = 0; i < 2; i++) {
                int idx = tid + i * 256;
                int key = idx >> 3, d4 = idx & 7;
                float4 v = kreg[i];
                float hv[4] = {trunc13(v.x), trunc13(v.y), trunc13(v.z), trunc13(v.w)};
                float lv[4] = {v.x - hv[0], v.y - hv[1], v.z - hv[2], v.w - hv[3]};
#pragma unroll
                for (int j = 0; j < 4; j++) {
                    int d = d4 * 4 + j;
                    sKThN[pKT(d, key)] = hv[j];
                    sKTlN[pKT(d, key)] = __uint_as_float(to_tf32(lv[j]));
                }
            }
        }

        // A3. V(t+1) cp.async into nbuf
        if (have_next) {
            const float* Vs = Vb + (size_t)(t + 1) * TK * CDIM;
            uint32_t vb0 = sb + OFF_V + (uint32_t)nbuf * 65536u;
#pragma unroll
            for (int i = 0; i < 16; i++) {
                int f = tid + i * 256;
                int key = f >> 6, n4 = f & 63;
                cp_async16(vb0 + (uint32_t)pV(key, n4 * 4) * 4u, Vs + (size_t)key * CDIM + n4 * 4);
            }
            asm volatile("cp.async.commit_group;" ::: "memory");
            asm volatile("cp.async.wait_group 1;" ::: "memory");   // V(t) done
        } else {
            asm volatile("cp.async.wait_group 0;" ::: "memory");
        }
        __syncthreads();   // sync1: P/sLp/KT(nbuf) visible, V(t) visible

        // B0. l accumulate
        if (tid < 128)
            sL[tid] += (sLp[tid] + sLp[128 + tid]) + (sLp[256 + tid] + sLp[384 + tid]);

        // B1. fused MMA block: QK(t+1) [ks 0..3] interleaved with PV(t) [ks 0..7]
        const float* sKTh = (const float*)(smem + OFF_KTH + nbuf * 8192);
        const float* sKTl = (const float*)(smem + OFF_KTL + nbuf * 8192);
        const uint32_t* sVb = sVu + (size_t)buf * 16384;

#pragma unroll
        for (int mt = 0; mt < 4; mt++)
#pragma unroll
            for (int nt = 0; nt < 2; nt++)
#pragma unroll
                for (int c = 0; c < 4; c++) sa[mt][nt][c] = 0.0f;

#pragma unroll
        for (int ks = 0; ks < 8; ks++) {
            const int k0 = ks * 8;
            // --- QK(t+1) chunk (first 4 ks) ---
            if (ks < 4 && have_next) {
                uint32_t bh[2][2], bl[2][2];
#pragma unroll
                for (int nt = 0; nt < 2; nt++) {
                    int key = nw * 16 + nt * 8 + g;
                    int i0 = pKT(k0 + l4, key), i1 = pKT(k0 + 4 + l4, key);
                    bh[nt][0] = __float_as_uint(sKTh[i0]);
                    bh[nt][1] = __float_as_uint(sKTh[i1]);
                    bl[nt][0] = __float_as_uint(sKTl[i0]);
                    bl[nt][1] = __float_as_uint(sKTl[i1]);
                }
#pragma unroll
                for (int mt = 0; mt < 4; mt++) {
                    int r0 = mw * 64 + mt * 16 + g;
                    uint32_t ah0 = __float_as_uint(sQh[pQ(r0, k0 + l4)]);
                    uint32_t ah1 = __float_as_uint(sQh[pQ(r0 + 8, k0 + l4)]);
                    uint32_t ah2 = __float_as_uint(sQh[pQ(r0, k0 + 4 + l4)]);
                    uint32_t ah3 = __float_as_uint(sQh[pQ(r0 + 8, k0 + 4 + l4)]);
                    uint32_t al0 = __float_as_uint(sQl[pQ(r0, k0 + l4)]);
                    uint32_t al1 = __float_as_uint(sQl[pQ(r0 + 8, k0 + l4)]);
                    uint32_t al2 = __float_as_uint(sQl[pQ(r0, k0 + 4 + l4)]);
                    uint32_t al3 = __float_as_uint(sQl[pQ(r0 + 8, k0 + 4 + l4)]);
#pragma unroll
                    for (int nt = 0; nt < 2; nt++) {
                        mma8(sa[mt][nt], ah0, ah1, ah2, ah3, bh[nt][0], bh[nt][1]);
                        mma8(sa[mt][nt], ah0, ah1, ah2, ah3, bl[nt][0], bl[nt][1]);
                        mma8(sa[mt][nt], al0, al1, al2, al3, bh[nt][0], bh[nt][1]);
                    }
                }
            }
            // --- PV(t) chunk ---
            {
                uint32_t pa[4][4];
#pragma unroll
                for (int mt = 0; mt < 4; mt++) {
                    int r0 = mw * 64 + mt * 16 + g;
                    pa[mt][0] = sPu[pP(r0, k0 + l4)];
                    pa[mt][1] = sPu[pP(r0 + 8, k0 + l4)];
                    pa[mt][2] = sPu[pP(r0, k0 + 4 + l4)];
                    pa[mt][3] = sPu[pP(r0 + 8, k0 + 4 + l4)];
                }
#pragma unroll
                for (int nt = 0; nt < 8; nt++) {
                    int n = nw * 64 + nt * 8 + g;
                    uint32_t b0 = sVb[pV(k0 + l4, n)];
                    uint32_t b1 = sVb[pV(k0 + 4 + l4, n)];
#pragma unroll
                    for (int mt = 0; mt < 4; mt++)
                        mma8(oa[mt][nt], pa[mt][0], pa[mt][1], pa[mt][2], pa[mt][3], b0, b1);
                }
            }
        }
        __syncthreads();   // sync2: P / KT / V buffers free for next iteration
    }

    // ---- epilogue: O/l + residual ----
#pragma unroll
    for (int mt = 0; mt < 4; mt++) {
        int r0 = mw * 64 + mt * 16 + g;
        float inv0 = 1.0f / sL[r0];
        float inv1 = 1.0f / sL[r0 + 8];
        size_t row0 = (size_t)b * SEQ + q0 + r0;
#pragma unroll
        for (int nt = 0; nt < 8; nt++) {
            int col = nw * 64 + nt * 8 + l4 * 2;
            const float2* x0 = (const float2*)(X + (row0)*CDIM + col);
            const float2* x1 = (const float2*)(X + (row0 + 8) * CDIM + col);
            float2 xv0 = *x0, xv1 = *x1;
            float2 o0, o1;
            o0.x = oa[mt][nt][0] * inv0 + xv0.x;
            o0.y = oa[mt][nt][1] * inv0 + xv0.y;
            o1.x = oa[mt][nt][2] * inv1 + xv1.x;
            o1.y = oa[mt][nt][3] * inv1 + xv1.y;
            *(float2*)(Out + (row0)*CDIM + col) = o0;
            *(float2*)(Out + (row0 + 8) * CDIM + col) = o1;
        }
    }
}

// ============================================================================
// Merged q+k projection (benched 33 µs)
// ============================================================================
__global__ __launch_bounds__(128)
void sgemm_qk(const float* __restrict__ A,
              const float* __restrict__ Wq, const float* __restrict__ bq,
              const float* __restrict__ Wk, const float* __restrict__ bk,
              float* __restrict__ Yq, float* __restrict__ Yk) {
    constexpr int BM = 64, BK = 16, BN = 32, TM = 4, TN = 4, TX = 8, NT = 128;
    __shared__ float As[BK][BM + 4];
    __shared__ float Bq[BK][BN];
    __shared__ float Bk[BK][BN];
    const int tid = threadIdx.x;
    const int tx = tid % TX, ty = tid / TX;
    const int m0 = blockIdx.x * BM;

    unsigned long long aq[TM][2], ak[TM][2];
#pragma unroll
    for (int i = 0; i < TM; i++) {
        aq[i][0] = aq[i][1] = 0ull;
        ak[i][0] = ak[i][1] = 0ull;
    }

    for (int k0 = 0; k0 < CDIM; k0 += BK) {
        for (int idx = tid; idx < BM * BK / 4; idx += NT) {
            int m = idx / (BK / 4), kq = idx % (BK / 4);
            float4 t4 = *(const float4*)(A + (size_t)(m0 + m) * CDIM + k0 + kq * 4);
            As[kq * 4 + 0][m] = t4.x; As[kq * 4 + 1][m] = t4.y;
            As[kq * 4 + 2][m] = t4.z; As[kq * 4 + 3][m] = t4.w;
        }
        for (int idx = tid; idx < BK * BN / 4; idx += NT) {
            int kk = idx / (BN / 4), nq = idx % (BN / 4);
            *(float4*)&Bq[kk][nq * 4] = *(const float4*)(Wq + (size_t)(k0 + kk) * DDIM + nq * 4);
            *(float4*)&Bk[kk][nq * 4] = *(const float4*)(Wk + (size_t)(k0 + kk) * DDIM + nq * 4);
        }
        __syncthreads();
#pragma unroll
        for (int kk = 0; kk < BK; kk++) {
            ulonglong2 bbq = *(const ulonglong2*)&Bq[kk][tx * TN];
            ulonglong2 bbk = *(const ulonglong2*)&Bk[kk][tx * TN];
#pragma unroll
            for (int i = 0; i < TM; i++) {
                float a = As[kk][ty * TM + i];
                unsigned long long a2 = pack2(a, a);
                aq[i][0] = ffma2(bbq.x, a2, aq[i][0]);
                aq[i][1] = ffma2(bbq.y, a2, aq[i][1]);
                ak[i][0] = ffma2(bbk.x, a2, ak[i][0]);
                ak[i][1] = ffma2(bbk.y, a2, ak[i][1]);
            }
        }
        __syncthreads();
    }
    float4 bq4 = *(const float4*)(bq + tx * TN);
    float4 bk4 = *(const float4*)(bk + tx * TN);
#pragma unroll
    for (int i = 0; i < TM; i++) {
        int m = m0 + ty * TM + i;
        float v0, v1, v2, v3;
        unpack2(aq[i][0], v0, v1);
        unpack2(aq[i][1], v2, v3);
        float4 o;
        o.x = v0 + bq4.x; o.y = v1 + bq4.y; o.z = v2 + bq4.z; o.w = v3 + bq4.w;
        *(float4*)(Yq + (size_t)m * DDIM + tx * TN) = o;
        unpack2(ak[i][0], v0, v1);
        unpack2(ak[i][1], v2, v3);
        o.x = v0 + bk4.x; o.y = v1 + bk4.y; o.z = v2 + bk4.z; o.w = v3 + bk4.w;
        *(float4*)(Yk + (size_t)m * DDIM + tx * TN) = o;
    }
}

// ============================================================================
// V projection GEMM (round-2, passing)
// ============================================================================
template<int BM, int BN, int BK, int TM, int TN>
__global__ void sgemm_bias_kernel(const float* __restrict__ A, const float* __restrict__ W,
                                  const float* __restrict__ bias, float* __restrict__ Y,
                                  int M, int Kd, int N) {
    __shared__ float As[BK][BM + 4];
    __shared__ float Bs[BK][BN];
    constexpr int TX = BN / TN;
    constexpr int NT = (BM / TM) * TX;
    const int tid = threadIdx.x;
    const int tx = tid % TX, ty = tid / TX;
    const int m0 = blockIdx.x * BM, n0 = blockIdx.y * BN;

    unsigned long long acc[TM][2];
#pragma unroll
    for (int i = 0; i < TM; i++) { acc[i][0] = 0ull; acc[i][1] = 0ull; }

    for (int k0 = 0; k0 < Kd; k0 += BK) {
        for (int idx = tid; idx < BM * BK / 4; idx += NT) {
            int m = idx / (BK / 4), kq = idx % (BK / 4);
            float4 t4 = *(const float4*)(A + (size_t)(m0 + m) * Kd + k0 + kq * 4);
            As[kq * 4 + 0][m] = t4.x; As[kq * 4 + 1][m] = t4.y;
            As[kq * 4 + 2][m] = t4.z; As[kq * 4 + 3][m] = t4.w;
        }
        for (int idx = tid; idx < BK * BN / 4; idx += NT) {
            int kk = idx / (BN / 4), nq = idx % (BN / 4);
            *(float4*)&Bs[kk][nq * 4] = *(const float4*)(W + (size_t)(k0 + kk) * N + n0 + nq * 4);
        }
        __syncthreads();
#pragma unroll
        for (int kk = 0; kk < BK; kk++) {
            ulonglong2 bb = *(const ulonglong2*)&Bs[kk][tx * TN];
#pragma unroll
            for (int i = 0; i < TM; i++) {
                float a = As[kk][ty * TM + i];
                unsigned long long a2 = pack2(a, a);
                acc[i][0] = ffma2(bb.x, a2, acc[i][0]);
                acc[i][1] = ffma2(bb.y, a2, acc[i][1]);
            }
        }
        __syncthreads();
    }
    float4 bv4 = *(const float4*)(bias + n0 + tx * TN);
#pragma unroll
    for (int i = 0; i < TM; i++) {
        int m = m0 + ty * TM + i;
        float v0, v1, v2, v3;
        unpack2(acc[i][0], v0, v1);
        unpack2(acc[i][1], v2, v3);
        float4 o;
        o.x = v0 + bv4.x; o.y = v1 + bv4.y; o.z = v2 + bv4.z; o.w = v3 + bv4.w;
        *(float4*)(Y + (size_t)m * N + n0 + tx * TN) = o;
    }
}

// ============================================================================
extern "C" void kernel_launch(void* const* d_in, const int* in_sizes, int n_in,
                              void* d_out, int out_size) {
    const float* x  = (const float*)d_in[0];
    const float* wq = (const float*)d_in[1];
    const float* bq = (const float*)d_in[2];
    const float* wk = (const float*)d_in[3];
    const float* bk = (const float*)d_in[4];
    const float* wv = (const float*)d_in[5];
    const float* bv = (const float*)d_in[6];
    float* out = (float*)d_out;

    float *qp, *kp, *vp;
    cudaGetSymbolAddress((void**)&qp, g_q);
    cudaGetSymbolAddress((void**)&kp, g_k);
    cudaGetSymbolAddress((void**)&vp, g_v);

    {
        dim3 g(BATCH * SEQ / 64, 1);
        sgemm_qk<<<g, 128>>>(x, wq, bq, wk, bk, qp, kp);
    }
    {
        dim3 g(BATCH * SEQ / 128, CDIM / 64);
        sgemm_bias_kernel<128, 64, 16, 8, 4><<<g, 256>>>(x, wv, bv, vp, BATCH * SEQ, CDIM, CDIM);
    }
    {
        cudaFuncSetAttribute(flash_mma, cudaFuncAttributeMaxDynamicSharedMemorySize, FLASH_SMEM);
        dim3 g(SEQ / TQ, BATCH);
        flash_mma<<<g, 256, FLASH_SMEM>>>(qp, kp, vp, x, out);
    }
}

// round 9
// speedup vs baseline: 1.3375x; 1.2390x over previous
#include <cuda_runtime.h>
#include <cstdint>

#define BATCH 4
#define SEQ   4096
#define CDIM  256
#define DDIM  32
#define TQ    128
#define TK    64
#define NT_TILES (SEQ / TK)

// ---- scratch ----
__device__ float g_q[BATCH * SEQ * DDIM];
__device__ float g_kth[BATCH * (SEQ / TK) * 32 * 64];   // K-hi, KT tile layout
__device__ float g_ktl[BATCH * (SEQ / TK) * 32 * 64];   // K-lo, KT tile layout
__device__ float g_v[BATCH * SEQ * CDIM];

// ---- helpers ----
__device__ __forceinline__ unsigned long long pack2(float lo, float hi) {
    unsigned long long r;
    asm("mov.b64 %0, {%1, %2};" : "=l"(r) : "f"(lo), "f"(hi));
    return r;
}
__device__ __forceinline__ void unpack2(unsigned long long v, float& lo, float& hi) {
    asm("mov.b64 {%0, %1}, %2;" : "=f"(lo), "=f"(hi) : "l"(v));
}
__device__ __forceinline__ unsigned long long ffma2(unsigned long long a, unsigned long long b,
                                                    unsigned long long c) {
    unsigned long long d;
    asm("fma.rn.f32x2 %0, %1, %2, %3;" : "=l"(d) : "l"(a), "l"(b), "l"(c));
    return d;
}
__device__ __forceinline__ uint32_t smem_u32(const void* p) {
    uint32_t a;
    asm("{ .reg .u64 t; cvta.to.shared.u64 t, %1; cvt.u32.u64 %0, t; }" : "=r"(a) : "l"(p));
    return a;
}
__device__ __forceinline__ void cp_async16(uint32_t dst, const void* src) {
    asm volatile("cp.async.cg.shared.global [%0], [%1], 16;" :: "r"(dst), "l"(src));
}
__device__ __forceinline__ uint32_t to_tf32(float f) {
    uint32_t u;
    asm("cvt.rna.tf32.f32 %0, %1;" : "=r"(u) : "f"(f));
    return u;
}
__device__ __forceinline__ float trunc13(float x) {
    return __uint_as_float(__float_as_uint(x) & 0xFFFFE000u);
}
__device__ __forceinline__ void mma8(float d[4], uint32_t a0, uint32_t a1, uint32_t a2,
                                     uint32_t a3, uint32_t b0, uint32_t b1) {
    asm volatile(
        "mma.sync.aligned.m16n8k8.row.col.f32.tf32.tf32.f32 "
        "{%0,%1,%2,%3}, {%4,%5,%6,%7}, {%8,%9}, {%0,%1,%2,%3};"
        : "+f"(d[0]), "+f"(d[1]), "+f"(d[2]), "+f"(d[3])
        : "r"(a0), "r"(a1), "r"(a2), "r"(a3), "r"(b0), "r"(b1));
}

// ---- smem byte offsets (round-5 layout, proven 349 us) ----
#define OFF_QHI 0
#define OFF_QLO 16384
#define OFF_KTH 32768
#define OFF_KTL 40960
#define OFF_P   49152
#define OFF_V   81920       /* 2 x 65536 */
#define OFF_L   212992
#define OFF_LP  213504
#define FLASH_SMEM 215552

// round-5 word-index swizzles (proven)
__device__ __forceinline__ int pQ(int r, int d)  { return r * 32 + (d ^ ((r & 7) * 4)); }
__device__ __forceinline__ int pKT(int d, int k) { return d * 64 + (k ^ ((d & 3) * 8)); }
__device__ __forceinline__ int pP(int r, int c)  { return r * 64 + (c ^ ((r & 7) * 4)); }
__device__ __forceinline__ int pV(int k, int n)  { return k * 256 + (n ^ ((k & 3) * 8)); }

// ============================================================================
// Flash attention on mma.sync tf32 (round-5 structure; K pre-split in gmem,
// loaded by cp.async into the identical smem image).
// 256 threads = 8 warps: mw = wid&1 (64 rows), nw = wid>>1 (16 keys / 64 PV cols)
// ============================================================================
__global__ __launch_bounds__(256, 1)
void flash_mma(const float* __restrict__ Qg,
               const float* __restrict__ KTHg, const float* __restrict__ KTLg,
               const float* __restrict__ Vg, const float* __restrict__ X,
               float* __restrict__ Out) {
    extern __shared__ char smem[];
    float*    sQh  = (float*)(smem + OFF_QHI);
    float*    sQl  = (float*)(smem + OFF_QLO);
    float*    sKTh = (float*)(smem + OFF_KTH);
    float*    sKTl = (float*)(smem + OFF_KTL);
    uint32_t* sPu  = (uint32_t*)(smem + OFF_P);
    uint32_t* sVu  = (uint32_t*)(smem + OFF_V);
    float*    sL   = (float*)(smem + OFF_L);
    float*    sLp  = (float*)(smem + OFF_LP);
    const uint32_t sb = smem_u32(smem);

    const int tid  = threadIdx.x;
    const int lane = tid & 31;
    const int wid  = tid >> 5;
    const int mw   = wid & 1;
    const int nw   = wid >> 1;
    const int g    = lane >> 2;
    const int l4   = lane & 3;
    const int b    = blockIdx.y;
    const int q0   = blockIdx.x * TQ;

    const float* Qb = Qg + ((size_t)b * SEQ + q0) * DDIM;
    const char*  KThb = (const char*)(KTHg + (size_t)b * NT_TILES * 2048);
    const char*  KTlb = (const char*)(KTLg + (size_t)b * NT_TILES * 2048);
    const float* Vb = Vg + (size_t)b * SEQ * CDIM;

    // ---- prologue ----
    if (tid < 128) sL[tid] = 0.0f;
    // Q hi/lo split
#pragma unroll
    for (int i = 0; i < 4; i++) {
        int idx = tid + i * 256;
        int r = idx >> 3, d4 = idx & 7;
        float4 v = *(const float4*)(Qb + r * DDIM + d4 * 4);
        float4 hi, lo;
        hi.x = trunc13(v.x); lo.x = __uint_as_float(to_tf32(v.x - hi.x));
        hi.y = trunc13(v.y); lo.y = __uint_as_float(to_tf32(v.y - hi.y));
        hi.z = trunc13(v.z); lo.z = __uint_as_float(to_tf32(v.z - hi.z));
        hi.w = trunc13(v.w); lo.w = __uint_as_float(to_tf32(v.w - hi.w));
        int base = r * 32 + ((d4 * 4) ^ ((r & 7) * 4));
        *(float4*)(sQh + base) = hi;
        *(float4*)(sQl + base) = lo;
    }
    // KT(0) + V(0) via cp.async (one group)
#pragma unroll
    for (int i = 0; i < 2; i++) {
        uint32_t off = (uint32_t)(tid + i * 256) * 16u;
        cp_async16(sb + OFF_KTH + off, KThb + off);
        cp_async16(sb + OFF_KTL + off, KTlb + off);
    }
#pragma unroll
    for (int i = 0; i < 16; i++) {
        int f = tid + i * 256;
        int key = f >> 6, n4 = f & 63;
        uint32_t dst = sb + OFF_V + (uint32_t)pV(key, n4 * 4) * 4u;
        cp_async16(dst, Vb + (size_t)key * CDIM + n4 * 4);
    }
    asm volatile("cp.async.commit_group;" ::: "memory");
    __syncthreads();

    float oa[4][8][4];
#pragma unroll
    for (int mt = 0; mt < 4; mt++)
#pragma unroll
        for (int nt = 0; nt < 8; nt++)
#pragma unroll
            for (int c = 0; c < 4; c++) oa[mt][nt][c] = 0.0f;

#pragma unroll 1
    for (int t = 0; t < NT_TILES; t++) {
        const int buf = t & 1;
        const bool have_next = (t + 1 < NT_TILES);

        // 1. V(t) + KT(t) ready
        asm volatile("cp.async.wait_group 0;" ::: "memory");
        __syncthreads();   // all threads see KT/V before compute (KT read below)

        // 2. prefetch V(t+1)
        if (have_next) {
            const float* Vs = Vb + (size_t)(t + 1) * TK * CDIM;
            uint32_t vb0 = sb + OFF_V + (uint32_t)(1 - buf) * 65536u;
#pragma unroll
            for (int i = 0; i < 16; i++) {
                int f = tid + i * 256;
                int key = f >> 6, n4 = f & 63;
                cp_async16(vb0 + (uint32_t)pV(key, n4 * 4) * 4u, Vs + (size_t)key * CDIM + n4 * 4);
            }
            asm volatile("cp.async.commit_group;" ::: "memory");
        }

        // 4. S = QK^T (compensated tf32)
        float sa[4][2][4];
#pragma unroll
        for (int mt = 0; mt < 4; mt++)
#pragma unroll
            for (int nt = 0; nt < 2; nt++)
#pragma unroll
                for (int c = 0; c < 4; c++) sa[mt][nt][c] = 0.0f;

#pragma unroll
        for (int ks = 0; ks < 4; ks++) {
            const int k0 = ks * 8;
            uint32_t bh[2][2], bl[2][2];
#pragma unroll
            for (int nt = 0; nt < 2; nt++) {
                int key = nw * 16 + nt * 8 + g;
                int i0 = pKT(k0 + l4, key), i1 = pKT(k0 + 4 + l4, key);
                bh[nt][0] = __float_as_uint(sKTh[i0]);
                bh[nt][1] = __float_as_uint(sKTh[i1]);
                bl[nt][0] = __float_as_uint(sKTl[i0]);
                bl[nt][1] = __float_as_uint(sKTl[i1]);
            }
#pragma unroll
            for (int mt = 0; mt < 4; mt++) {
                int r0 = mw * 64 + mt * 16 + g;
                uint32_t ah0 = __float_as_uint(sQh[pQ(r0, k0 + l4)]);
                uint32_t ah1 = __float_as_uint(sQh[pQ(r0 + 8, k0 + l4)]);
                uint32_t ah2 = __float_as_uint(sQh[pQ(r0, k0 + 4 + l4)]);
                uint32_t ah3 = __float_as_uint(sQh[pQ(r0 + 8, k0 + 4 + l4)]);
                uint32_t al0 = __float_as_uint(sQl[pQ(r0, k0 + l4)]);
                uint32_t al1 = __float_as_uint(sQl[pQ(r0 + 8, k0 + l4)]);
                uint32_t al2 = __float_as_uint(sQl[pQ(r0, k0 + 4 + l4)]);
                uint32_t al3 = __float_as_uint(sQl[pQ(r0 + 8, k0 + 4 + l4)]);
#pragma unroll
                for (int nt = 0; nt < 2; nt++) {
                    mma8(sa[mt][nt], ah0, ah1, ah2, ah3, bh[nt][0], bh[nt][1]);
                    mma8(sa[mt][nt], ah0, ah1, ah2, ah3, bl[nt][0], bl[nt][1]);
                    mma8(sa[mt][nt], al0, al1, al2, al3, bh[nt][0], bh[nt][1]);
                }
            }
        }

        // 5. exp (no max), P -> smem (tf32), partial row sums
#pragma unroll
        for (int mt = 0; mt < 4; mt++) {
            int r0 = mw * 64 + mt * 16 + g;
            float s0 = 0.0f, s1 = 0.0f;
#pragma unroll
            for (int nt = 0; nt < 2; nt++) {
                int col = nw * 16 + nt * 8 + l4 * 2;
                uint32_t e0 = to_tf32(__expf(sa[mt][nt][0]));
                uint32_t e1 = to_tf32(__expf(sa[mt][nt][1]));
                uint32_t e2 = to_tf32(__expf(sa[mt][nt][2]));
                uint32_t e3 = to_tf32(__expf(sa[mt][nt][3]));
                s0 += __uint_as_float(e0) + __uint_as_float(e1);
                s1 += __uint_as_float(e2) + __uint_as_float(e3);
                sPu[pP(r0, col)]     = e0;
                sPu[pP(r0, col + 1)] = e1;
                sPu[pP(r0 + 8, col)]     = e2;
                sPu[pP(r0 + 8, col + 1)] = e3;
            }
            s0 += __shfl_xor_sync(0xffffffffu, s0, 1);
            s0 += __shfl_xor_sync(0xffffffffu, s0, 2);
            s1 += __shfl_xor_sync(0xffffffffu, s1, 1);
            s1 += __shfl_xor_sync(0xffffffffu, s1, 2);
            if (l4 == 0) {
                sLp[nw * 128 + r0] = s0;
                sLp[nw * 128 + r0 + 8] = s1;
            }
        }
        __syncthreads();   // sync1: sP/sLp visible; KT buffer free for overwrite

        // 6. cp.async KT(t+1) (replaces register staging + STS) + l accumulate
        if (have_next) {
            const char* kth_t = KThb + (size_t)(t + 1) * 8192;
            const char* ktl_t = KTlb + (size_t)(t + 1) * 8192;
#pragma unroll
            for (int i = 0; i < 2; i++) {
                uint32_t off = (uint32_t)(tid + i * 256) * 16u;
                cp_async16(sb + OFF_KTH + off, kth_t + off);
                cp_async16(sb + OFF_KTL + off, ktl_t + off);
            }
            asm volatile("cp.async.commit_group;" ::: "memory");
        }
        if (tid < 128)
            sL[tid] += (sLp[tid] + sLp[128 + tid]) + (sLp[256 + tid] + sLp[384 + tid]);

        // 7. O += P @ V
        const uint32_t* sVb = sVu + (size_t)buf * 16384;
#pragma unroll
        for (int ks = 0; ks < 8; ks++) {
            const int k0 = ks * 8;
            uint32_t pa[4][4];
#pragma unroll
            for (int mt = 0; mt < 4; mt++) {
                int r0 = mw * 64 + mt * 16 + g;
                pa[mt][0] = sPu[pP(r0, k0 + l4)];
                pa[mt][1] = sPu[pP(r0 + 8, k0 + l4)];
                pa[mt][2] = sPu[pP(r0, k0 + 4 + l4)];
                pa[mt][3] = sPu[pP(r0 + 8, k0 + 4 + l4)];
            }
#pragma unroll
            for (int nt = 0; nt < 8; nt++) {
                int n = nw * 64 + nt * 8 + g;
                uint32_t b0 = sVb[pV(k0 + l4, n)];
                uint32_t b1 = sVb[pV(k0 + 4 + l4, n)];
#pragma unroll
                for (int mt = 0; mt < 4; mt++)
                    mma8(oa[mt][nt], pa[mt][0], pa[mt][1], pa[mt][2], pa[mt][3], b0, b1);
            }
        }
        __syncthreads();   // sync2: sP free; V(t) buffer free next iteration
    }

    // ---- epilogue: O/l + residual ----
#pragma unroll
    for (int mt = 0; mt < 4; mt++) {
        int r0 = mw * 64 + mt * 16 + g;
        float inv0 = 1.0f / sL[r0];
        float inv1 = 1.0f / sL[r0 + 8];
        size_t row0 = (size_t)b * SEQ + q0 + r0;
#pragma unroll
        for (int nt = 0; nt < 8; nt++) {
            int col = nw * 64 + nt * 8 + l4 * 2;
            const float2* x0 = (const float2*)(X + (row0)*CDIM + col);
            const float2* x1 = (const float2*)(X + (row0 + 8) * CDIM + col);
            float2 xv0 = *x0, xv1 = *x1;
            float2 o0, o1;
            o0.x = oa[mt][nt][0] * inv0 + xv0.x;
            o0.y = oa[mt][nt][1] * inv0 + xv0.y;
            o1.x = oa[mt][nt][2] * inv1 + xv1.x;
            o1.y = oa[mt][nt][3] * inv1 + xv1.y;
            *(float2*)(Out + (row0)*CDIM + col) = o0;
            *(float2*)(Out + (row0 + 8) * CDIM + col) = o1;
        }
    }
}

// ============================================================================
// Merged q+k projection; k output written pre-split (hi/lo) in KT tile layout.
// ============================================================================
__global__ __launch_bounds__(128)
void sgemm_qk(const float* __restrict__ A,
              const float* __restrict__ Wq, const float* __restrict__ bq,
              const float* __restrict__ Wk, const float* __restrict__ bk,
              float* __restrict__ Yq, float* __restrict__ KTH, float* __restrict__ KTL) {
    constexpr int BM = 64, BK = 16, BN = 32, TM = 4, TN = 4, TX = 8, NT = 128;
    __shared__ float As[BK][BM + 4];
    __shared__ float Bq[BK][BN];
    __shared__ float Bk[BK][BN];
    const int tid = threadIdx.x;
    const int tx = tid % TX, ty = tid / TX;
    const int m0 = blockIdx.x * BM;

    unsigned long long aq[TM][2], ak[TM][2];
#pragma unroll
    for (int i = 0; i < TM; i++) {
        aq[i][0] = aq[i][1] = 0ull;
        ak[i][0] = ak[i][1] = 0ull;
    }

    for (int k0 = 0; k0 < CDIM; k0 += BK) {
        for (int idx = tid; idx < BM * BK / 4; idx += NT) {
            int m = idx / (BK / 4), kq = idx % (BK / 4);
            float4 t4 = *(const float4*)(A + (size_t)(m0 + m) * CDIM + k0 + kq * 4);
            As[kq * 4 + 0][m] = t4.x; As[kq * 4 + 1][m] = t4.y;
            As[kq * 4 + 2][m] = t4.z; As[kq * 4 + 3][m] = t4.w;
        }
        for (int idx = tid; idx < BK * BN / 4; idx += NT) {
            int kk = idx / (BN / 4), nq = idx % (BN / 4);
            *(float4*)&Bq[kk][nq * 4] = *(const float4*)(Wq + (size_t)(k0 + kk) * DDIM + nq * 4);
            *(float4*)&Bk[kk][nq * 4] = *(const float4*)(Wk + (size_t)(k0 + kk) * DDIM + nq * 4);
        }
        __syncthreads();
#pragma unroll
        for (int kk = 0; kk < BK; kk++) {
            ulonglong2 bbq = *(const ulonglong2*)&Bq[kk][tx * TN];
            ulonglong2 bbk = *(const ulonglong2*)&Bk[kk][tx * TN];
#pragma unroll
            for (int i = 0; i < TM; i++) {
                float a = As[kk][ty * TM + i];
                unsigned long long a2 = pack2(a, a);
                aq[i][0] = ffma2(bbq.x, a2, aq[i][0]);
                aq[i][1] = ffma2(bbq.y, a2, aq[i][1]);
                ak[i][0] = ffma2(bbk.x, a2, ak[i][0]);
                ak[i][1] = ffma2(bbk.y, a2, ak[i][1]);
            }
        }
        __syncthreads();
    }
    float4 bq4 = *(const float4*)(bq + tx * TN);
    float4 bk4 = *(const float4*)(bk + tx * TN);
#pragma unroll
    for (int i = 0; i < TM; i++) {
        int m = m0 + ty * TM + i;
        float v0, v1, v2, v3;
        // q output (plain layout)
        unpack2(aq[i][0], v0, v1);
        unpack2(aq[i][1], v2, v3);
        float4 o;
        o.x = v0 + bq4.x; o.y = v1 + bq4.y; o.z = v2 + bq4.z; o.w = v3 + bq4.w;
        *(float4*)(Yq + (size_t)m * DDIM + tx * TN) = o;
        // k output: hi/lo split into KT tile layout
        float kv[4];
        unpack2(ak[i][0], kv[0], kv[1]);
        unpack2(ak[i][1], kv[2], kv[3]);
        kv[0] += bk4.x; kv[1] += bk4.y; kv[2] += bk4.z; kv[3] += bk4.w;
        int key = m & 63;
        size_t base = (size_t)(m >> 6) * 2048;
#pragma unroll
        for (int j = 0; j < 4; j++) {
            int d = tx * 4 + j;
            float hi = trunc13(kv[j]);
            float lo = __uint_as_float(to_tf32(kv[j] - hi));
            size_t w = base + (size_t)(d * 64 + (key ^ ((d & 3) * 8)));
            KTH[w] = hi;
            KTL[w] = lo;
        }
    }
}

// ============================================================================
// V projection GEMM (round-2, passing)
// ============================================================================
template<int BM, int BN, int BK, int TM, int TN>
__global__ void sgemm_bias_kernel(const float* __restrict__ A, const float* __restrict__ W,
                                  const float* __restrict__ bias, float* __restrict__ Y,
                                  int M, int Kd, int N) {
    __shared__ float As[BK][BM + 4];
    __shared__ float Bs[BK][BN];
    constexpr int TX = BN / TN;
    constexpr int NT = (BM / TM) * TX;
    const int tid = threadIdx.x;
    const int tx = tid % TX, ty = tid / TX;
    const int m0 = blockIdx.x * BM, n0 = blockIdx.y * BN;

    unsigned long long acc[TM][2];
#pragma unroll
    for (int i = 0; i < TM; i++) { acc[i][0] = 0ull; acc[i][1] = 0ull; }

    for (int k0 = 0; k0 < Kd; k0 += BK) {
        for (int idx = tid; idx < BM * BK / 4; idx += NT) {
            int m = idx / (BK / 4), kq = idx % (BK / 4);
            float4 t4 = *(const float4*)(A + (size_t)(m0 + m) * Kd + k0 + kq * 4);
            As[kq * 4 + 0][m] = t4.x; As[kq * 4 + 1][m] = t4.y;
            As[kq * 4 + 2][m] = t4.z; As[kq * 4 + 3][m] = t4.w;
        }
        for (int idx = tid; idx < BK * BN / 4; idx += NT) {
            int kk = idx / (BN / 4), nq = idx % (BN / 4);
            *(float4*)&Bs[kk][nq * 4] = *(const float4*)(W + (size_t)(k0 + kk) * N + n0 + nq * 4);
        }
        __syncthreads();
#pragma unroll
        for (int kk = 0; kk < BK; kk++) {
            ulonglong2 bb = *(const ulonglong2*)&Bs[kk][tx * TN];
#pragma unroll
            for (int i = 0; i < TM; i++) {
                float a = As[kk][ty * TM + i];
                unsigned long long a2 = pack2(a, a);
                acc[i][0] = ffma2(bb.x, a2, acc[i][0]);
                acc[i][1] = ffma2(bb.y, a2, acc[i][1]);
            }
        }
        __syncthreads();
    }
    float4 bv4 = *(const float4*)(bias + n0 + tx * TN);
#pragma unroll
    for (int i = 0; i < TM; i++) {
        int m = m0 + ty * TM + i;
        float v0, v1, v2, v3;
        unpack2(acc[i][0], v0, v1);
        unpack2(acc[i][1], v2, v3);
        float4 o;
        o.x = v0 + bv4.x; o.y = v1 + bv4.y; o.z = v2 + bv4.z; o.w = v3 + bv4.w;
        *(float4*)(Y + (size_t)m * N + n0 + tx * TN) = o;
    }
}

// ============================================================================
extern "C" void kernel_launch(void* const* d_in, const int* in_sizes, int n_in,
                              void* d_out, int out_size) {
    const float* x  = (const float*)d_in[0];
    const float* wq = (const float*)d_in[1];
    const float* bq = (const float*)d_in[2];
    const float* wk = (const float*)d_in[3];
    const float* bk = (const float*)d_in[4];
    const float* wv = (const float*)d_in[5];
    const float* bv = (const float*)d_in[6];
    float* out = (float*)d_out;

    float *qp, *kthp, *ktlp, *vp;
    cudaGetSymbolAddress((void**)&qp, g_q);
    cudaGetSymbolAddress((void**)&kthp, g_kth);
    cudaGetSymbolAddress((void**)&ktlp, g_ktl);
    cudaGetSymbolAddress((void**)&vp, g_v);

    {
        dim3 g(BATCH * SEQ / 64, 1);
        sgemm_qk<<<g, 128>>>(x, wq, bq, wk, bk, qp, kthp, ktlp);
    }
    {
        dim3 g(BATCH * SEQ / 128, CDIM / 64);
        sgemm_bias_kernel<128, 64, 16, 8, 4><<<g, 256>>>(x, wv, bv, vp, BATCH * SEQ, CDIM, CDIM);
    }
    {
        cudaFuncSetAttribute(flash_mma, cudaFuncAttributeMaxDynamicSharedMemorySize, FLASH_SMEM);
        dim3 g(SEQ / TQ, BATCH);
        flash_mma<<<g, 256, FLASH_SMEM>>>(qp, kthp, ktlp, vp, x, out);
    }
}

// round 10
// speedup vs baseline: 1.3394x; 1.0014x over previous
#include <cuda_runtime.h>
#include <cstdint>

#define BATCH 4
#define SEQ   4096
#define CDIM  256
#define DDIM  32
#define TQ    128
#define TK    64
#define NT_TILES (SEQ / TK)
#define LOG2E 1.4426950408889634f

// ---- scratch ----
__device__ float g_q[BATCH * SEQ * DDIM];
__device__ float g_kth[BATCH * (SEQ / TK) * 32 * 64];   // K-hi, KT tile layout
__device__ float g_ktl[BATCH * (SEQ / TK) * 32 * 64];   // K-lo, KT tile layout
__device__ float g_v[BATCH * SEQ * CDIM];

// ---- helpers ----
__device__ __forceinline__ unsigned long long pack2(float lo, float hi) {
    unsigned long long r;
    asm("mov.b64 %0, {%1, %2};" : "=l"(r) : "f"(lo), "f"(hi));
    return r;
}
__device__ __forceinline__ void unpack2(unsigned long long v, float& lo, float& hi) {
    asm("mov.b64 {%0, %1}, %2;" : "=f"(lo), "=f"(hi) : "l"(v));
}
__device__ __forceinline__ unsigned long long ffma2(unsigned long long a, unsigned long long b,
                                                    unsigned long long c) {
    unsigned long long d;
    asm("fma.rn.f32x2 %0, %1, %2, %3;" : "=l"(d) : "l"(a), "l"(b), "l"(c));
    return d;
}
__device__ __forceinline__ uint32_t smem_u32(const void* p) {
    uint32_t a;
    asm("{ .reg .u64 t; cvta.to.shared.u64 t, %1; cvt.u32.u64 %0, t; }" : "=r"(a) : "l"(p));
    return a;
}
__device__ __forceinline__ void cp_async16(uint32_t dst, const void* src) {
    asm volatile("cp.async.cg.shared.global [%0], [%1], 16;" :: "r"(dst), "l"(src));
}
__device__ __forceinline__ uint32_t to_tf32(float f) {
    uint32_t u;
    asm("cvt.rna.tf32.f32 %0, %1;" : "=r"(u) : "f"(f));
    return u;
}
__device__ __forceinline__ float trunc13(float x) {
    return __uint_as_float(__float_as_uint(x) & 0xFFFFE000u);
}
__device__ __forceinline__ float ex2(float x) {
    float r;
    asm("ex2.approx.f32 %0, %1;" : "=f"(r) : "f"(x));
    return r;
}
__device__ __forceinline__ void mma8(float d[4], uint32_t a0, uint32_t a1, uint32_t a2,
                                     uint32_t a3, uint32_t b0, uint32_t b1) {
    asm volatile(
        "mma.sync.aligned.m16n8k8.row.col.f32.tf32.tf32.f32 "
        "{%0,%1,%2,%3}, {%4,%5,%6,%7}, {%8,%9}, {%0,%1,%2,%3};"
        : "+f"(d[0]), "+f"(d[1]), "+f"(d[2]), "+f"(d[3])
        : "r"(a0), "r"(a1), "r"(a2), "r"(a3), "r"(b0), "r"(b1));
}

// ---- smem byte offsets (round-5 layout, proven) ----
#define OFF_QHI 0
#define OFF_QLO 16384
#define OFF_KTH 32768
#define OFF_KTL 40960
#define OFF_P   49152
#define OFF_V   81920       /* 2 x 65536 */
#define OFF_L   212992
#define OFF_LP  213504
#define FLASH_SMEM 215552

// round-5 word-index swizzles (proven)
__device__ __forceinline__ int pQ(int r, int d)  { return r * 32 + (d ^ ((r & 7) * 4)); }
__device__ __forceinline__ int pKT(int d, int k) { return d * 64 + (k ^ ((d & 3) * 8)); }
__device__ __forceinline__ int pP(int r, int c)  { return r * 64 + (c ^ ((r & 7) * 4)); }
__device__ __forceinline__ int pV(int k, int n)  { return k * 256 + (n ^ ((k & 3) * 8)); }

// ============================================================================
// Flash attention on mma.sync tf32 (round-9 structure; 2 barriers/tile,
// log2e folded into Q, P truncated by AND + stored via STS.64).
// 256 threads = 8 warps: mw = wid&1 (64 rows), nw = wid>>1 (16 keys / 64 PV cols)
// ============================================================================
__global__ __launch_bounds__(256, 1)
void flash_mma(const float* __restrict__ Qg,
               const float* __restrict__ KTHg, const float* __restrict__ KTLg,
               const float* __restrict__ Vg, const float* __restrict__ X,
               float* __restrict__ Out) {
    extern __shared__ char smem[];
    float*    sQh  = (float*)(smem + OFF_QHI);
    float*    sQl  = (float*)(smem + OFF_QLO);
    float*    sKTh = (float*)(smem + OFF_KTH);
    float*    sKTl = (float*)(smem + OFF_KTL);
    uint32_t* sPu  = (uint32_t*)(smem + OFF_P);
    uint32_t* sVu  = (uint32_t*)(smem + OFF_V);
    float*    sL   = (float*)(smem + OFF_L);
    float*    sLp  = (float*)(smem + OFF_LP);
    const uint32_t sb = smem_u32(smem);

    const int tid  = threadIdx.x;
    const int lane = tid & 31;
    const int wid  = tid >> 5;
    const int mw   = wid & 1;
    const int nw   = wid >> 1;
    const int g    = lane >> 2;
    const int l4   = lane & 3;
    const int b    = blockIdx.y;
    const int q0   = blockIdx.x * TQ;

    const float* Qb = Qg + ((size_t)b * SEQ + q0) * DDIM;
    const char*  KThb = (const char*)(KTHg + (size_t)b * NT_TILES * 2048);
    const char*  KTlb = (const char*)(KTLg + (size_t)b * NT_TILES * 2048);
    const float* Vb = Vg + (size_t)b * SEQ * CDIM;

    // ---- prologue ----
    if (tid < 128) sL[tid] = 0.0f;
    // Q scaled by log2e, then hi/lo split (hi tf32-exact)
#pragma unroll
    for (int i = 0; i < 4; i++) {
        int idx = tid + i * 256;
        int r = idx >> 3, d4 = idx & 7;
        float4 v = *(const float4*)(Qb + r * DDIM + d4 * 4);
        v.x *= LOG2E; v.y *= LOG2E; v.z *= LOG2E; v.w *= LOG2E;
        float4 hi, lo;
        hi.x = trunc13(v.x); lo.x = __uint_as_float(to_tf32(v.x - hi.x));
        hi.y = trunc13(v.y); lo.y = __uint_as_float(to_tf32(v.y - hi.y));
        hi.z = trunc13(v.z); lo.z = __uint_as_float(to_tf32(v.z - hi.z));
        hi.w = trunc13(v.w); lo.w = __uint_as_float(to_tf32(v.w - hi.w));
        int base = r * 32 + ((d4 * 4) ^ ((r & 7) * 4));
        *(float4*)(sQh + base) = hi;
        *(float4*)(sQl + base) = lo;
    }
    // KT(0) + V(0) via cp.async (one group)
#pragma unroll
    for (int i = 0; i < 2; i++) {
        uint32_t off = (uint32_t)(tid + i * 256) * 16u;
        cp_async16(sb + OFF_KTH + off, KThb + off);
        cp_async16(sb + OFF_KTL + off, KTlb + off);
    }
#pragma unroll
    for (int i = 0; i < 16; i++) {
        int f = tid + i * 256;
        int key = f >> 6, n4 = f & 63;
        uint32_t dst = sb + OFF_V + (uint32_t)pV(key, n4 * 4) * 4u;
        cp_async16(dst, Vb + (size_t)key * CDIM + n4 * 4);
    }
    asm volatile("cp.async.commit_group;" ::: "memory");
    asm volatile("cp.async.wait_group 0;" ::: "memory");
    __syncthreads();

    float oa[4][8][4];
#pragma unroll
    for (int mt = 0; mt < 4; mt++)
#pragma unroll
        for (int nt = 0; nt < 8; nt++)
#pragma unroll
            for (int c = 0; c < 4; c++) oa[mt][nt][c] = 0.0f;

#pragma unroll 1
    for (int t = 0; t < NT_TILES; t++) {
        const int buf = t & 1;
        const bool have_next = (t + 1 < NT_TILES);

        // 1. prefetch V(t+1) into the other buffer
        if (have_next) {
            const float* Vs = Vb + (size_t)(t + 1) * TK * CDIM;
            uint32_t vb0 = sb + OFF_V + (uint32_t)(1 - buf) * 65536u;
#pragma unroll
            for (int i = 0; i < 16; i++) {
                int f = tid + i * 256;
                int key = f >> 6, n4 = f & 63;
                cp_async16(vb0 + (uint32_t)pV(key, n4 * 4) * 4u, Vs + (size_t)key * CDIM + n4 * 4);
            }
            asm volatile("cp.async.commit_group;" ::: "memory");
        }

        // 2. S = QK^T (compensated tf32); result is log2e * scores
        float sa[4][2][4];
#pragma unroll
        for (int mt = 0; mt < 4; mt++)
#pragma unroll
            for (int nt = 0; nt < 2; nt++)
#pragma unroll
                for (int c = 0; c < 4; c++) sa[mt][nt][c] = 0.0f;

#pragma unroll
        for (int ks = 0; ks < 4; ks++) {
            const int k0 = ks * 8;
            uint32_t bh[2][2], bl[2][2];
#pragma unroll
            for (int nt = 0; nt < 2; nt++) {
                int key = nw * 16 + nt * 8 + g;
                int i0 = pKT(k0 + l4, key), i1 = pKT(k0 + 4 + l4, key);
                bh[nt][0] = __float_as_uint(sKTh[i0]);
                bh[nt][1] = __float_as_uint(sKTh[i1]);
                bl[nt][0] = __float_as_uint(sKTl[i0]);
                bl[nt][1] = __float_as_uint(sKTl[i1]);
            }
#pragma unroll
            for (int mt = 0; mt < 4; mt++) {
                int r0 = mw * 64 + mt * 16 + g;
                uint32_t ah0 = __float_as_uint(sQh[pQ(r0, k0 + l4)]);
                uint32_t ah1 = __float_as_uint(sQh[pQ(r0 + 8, k0 + l4)]);
                uint32_t ah2 = __float_as_uint(sQh[pQ(r0, k0 + 4 + l4)]);
                uint32_t ah3 = __float_as_uint(sQh[pQ(r0 + 8, k0 + 4 + l4)]);
                uint32_t al0 = __float_as_uint(sQl[pQ(r0, k0 + l4)]);
                uint32_t al1 = __float_as_uint(sQl[pQ(r0 + 8, k0 + l4)]);
                uint32_t al2 = __float_as_uint(sQl[pQ(r0, k0 + 4 + l4)]);
                uint32_t al3 = __float_as_uint(sQl[pQ(r0 + 8, k0 + 4 + l4)]);
#pragma unroll
                for (int nt = 0; nt < 2; nt++) {
                    mma8(sa[mt][nt], ah0, ah1, ah2, ah3, bh[nt][0], bh[nt][1]);
                    mma8(sa[mt][nt], ah0, ah1, ah2, ah3, bl[nt][0], bl[nt][1]);
                    mma8(sa[mt][nt], al0, al1, al2, al3, bh[nt][0], bh[nt][1]);
                }
            }
        }

        // 3. p = 2^s (no max); truncate to tf32 bits via AND; STS.64 pairs
#pragma unroll
        for (int mt = 0; mt < 4; mt++) {
            int r0 = mw * 64 + mt * 16 + g;
            float s0 = 0.0f, s1 = 0.0f;
#pragma unroll
            for (int nt = 0; nt < 2; nt++) {
                int col = nw * 16 + nt * 8 + l4 * 2;
                uint32_t e0 = __float_as_uint(ex2(sa[mt][nt][0])) & 0xFFFFE000u;
                uint32_t e1 = __float_as_uint(ex2(sa[mt][nt][1])) & 0xFFFFE000u;
                uint32_t e2 = __float_as_uint(ex2(sa[mt][nt][2])) & 0xFFFFE000u;
                uint32_t e3 = __float_as_uint(ex2(sa[mt][nt][3])) & 0xFFFFE000u;
                s0 += __uint_as_float(e0) + __uint_as_float(e1);
                s1 += __uint_as_float(e2) + __uint_as_float(e3);
                uint2 w0; w0.x = e0; w0.y = e1;
                uint2 w1; w1.x = e2; w1.y = e3;
                *(uint2*)(sPu + pP(r0, col)) = w0;
                *(uint2*)(sPu + pP(r0 + 8, col)) = w1;
            }
            s0 += __shfl_xor_sync(0xffffffffu, s0, 1);
            s0 += __shfl_xor_sync(0xffffffffu, s0, 2);
            s1 += __shfl_xor_sync(0xffffffffu, s1, 1);
            s1 += __shfl_xor_sync(0xffffffffu, s1, 2);
            if (l4 == 0) {
                sLp[nw * 128 + r0] = s0;
                sLp[nw * 128 + r0 + 8] = s1;
            }
        }
        __syncthreads();   // sync1: sP/sLp visible; KT buffer free for overwrite

        // 4. cp.async KT(t+1) + l accumulate
        if (have_next) {
            const char* kth_t = KThb + (size_t)(t + 1) * 8192;
            const char* ktl_t = KTlb + (size_t)(t + 1) * 8192;
#pragma unroll
            for (int i = 0; i < 2; i++) {
                uint32_t off = (uint32_t)(tid + i * 256) * 16u;
                cp_async16(sb + OFF_KTH + off, kth_t + off);
                cp_async16(sb + OFF_KTL + off, ktl_t + off);
            }
            asm volatile("cp.async.commit_group;" ::: "memory");
        }
        if (tid < 128)
            sL[tid] += (sLp[tid] + sLp[128 + tid]) + (sLp[256 + tid] + sLp[384 + tid]);

        // 5. O += P @ V
        const uint32_t* sVb = sVu + (size_t)buf * 16384;
#pragma unroll
        for (int ks = 0; ks < 8; ks++) {
            const int k0 = ks * 8;
            uint32_t pa[4][4];
#pragma unroll
            for (int mt = 0; mt < 4; mt++) {
                int r0 = mw * 64 + mt * 16 + g;
                pa[mt][0] = sPu[pP(r0, k0 + l4)];
                pa[mt][1] = sPu[pP(r0 + 8, k0 + l4)];
                pa[mt][2] = sPu[pP(r0, k0 + 4 + l4)];
                pa[mt][3] = sPu[pP(r0 + 8, k0 + 4 + l4)];
            }
#pragma unroll
            for (int nt = 0; nt < 8; nt++) {
                int n = nw * 64 + nt * 8 + g;
                uint32_t b0 = sVb[pV(k0 + l4, n)];
                uint32_t b1 = sVb[pV(k0 + 4 + l4, n)];
#pragma unroll
                for (int mt = 0; mt < 4; mt++)
                    mma8(oa[mt][nt], pa[mt][0], pa[mt][1], pa[mt][2], pa[mt][3], b0, b1);
            }
        }

        // 6. V(t+1)+KT(t+1) landed; make visible and free sP/V(t)
        asm volatile("cp.async.wait_group 0;" ::: "memory");
        __syncthreads();   // sync2
    }

    // ---- epilogue: O/l + residual ----
#pragma unroll
    for (int mt = 0; mt < 4; mt++) {
        int r0 = mw * 64 + mt * 16 + g;
        float inv0 = 1.0f / sL[r0];
        float inv1 = 1.0f / sL[r0 + 8];
        size_t row0 = (size_t)b * SEQ + q0 + r0;
#pragma unroll
        for (int nt = 0; nt < 8; nt++) {
            int col = nw * 64 + nt * 8 + l4 * 2;
            const float2* x0 = (const float2*)(X + (row0)*CDIM + col);
            const float2* x1 = (const float2*)(X + (row0 + 8) * CDIM + col);
            float2 xv0 = *x0, xv1 = *x1;
            float2 o0, o1;
            o0.x = oa[mt][nt][0] * inv0 + xv0.x;
            o0.y = oa[mt][nt][1] * inv0 + xv0.y;
            o1.x = oa[mt][nt][2] * inv1 + xv1.x;
            o1.y = oa[mt][nt][3] * inv1 + xv1.y;
            *(float2*)(Out + (row0)*CDIM + col) = o0;
            *(float2*)(Out + (row0 + 8) * CDIM + col) = o1;
        }
    }
}

// ============================================================================
// Merged q+k projection, 256 threads (8 warps) for latency hiding.
// k output written pre-split (hi/lo) in KT tile layout.
// ============================================================================
__global__ __launch_bounds__(256)
void sgemm_qk(const float* __restrict__ A,
              const float* __restrict__ Wq, const float* __restrict__ bq,
              const float* __restrict__ Wk, const float* __restrict__ bk,
              float* __restrict__ Yq, float* __restrict__ KTH, float* __restrict__ KTL) {
    constexpr int BM = 64, BK = 16, BN = 32, TM = 2, TN = 4, TX = 8;
    __shared__ float As[BK][BM + 4];
    __shared__ float Bq[BK][BN];
    __shared__ float Bk[BK][BN];
    const int tid = threadIdx.x;
    const int tx = tid % TX, ty = tid / TX;   // ty 0..31
    const int m0 = blockIdx.x * BM;

    unsigned long long aq[TM][2], ak[TM][2];
#pragma unroll
    for (int i = 0; i < TM; i++) {
        aq[i][0] = aq[i][1] = 0ull;
        ak[i][0] = ak[i][1] = 0ull;
    }

    for (int k0 = 0; k0 < CDIM; k0 += BK) {
        {   // As: 256 float4 loads, exactly one per thread
            int m = tid >> 2, kq = tid & 3;
            float4 t4 = *(const float4*)(A + (size_t)(m0 + m) * CDIM + k0 + kq * 4);
            As[kq * 4 + 0][m] = t4.x; As[kq * 4 + 1][m] = t4.y;
            As[kq * 4 + 2][m] = t4.z; As[kq * 4 + 3][m] = t4.w;
        }
        if (tid < 128) {
            int kk = tid >> 3, nq = tid & 7;
            *(float4*)&Bq[kk][nq * 4] = *(const float4*)(Wq + (size_t)(k0 + kk) * DDIM + nq * 4);
            *(float4*)&Bk[kk][nq * 4] = *(const float4*)(Wk + (size_t)(k0 + kk) * DDIM + nq * 4);
        }
        __syncthreads();
#pragma unroll
        for (int kk = 0; kk < BK; kk++) {
            ulonglong2 bbq = *(const ulonglong2*)&Bq[kk][tx * TN];
            ulonglong2 bbk = *(const ulonglong2*)&Bk[kk][tx * TN];
#pragma unroll
            for (int i = 0; i < TM; i++) {
                float a = As[kk][ty * TM + i];
                unsigned long long a2 = pack2(a, a);
                aq[i][0] = ffma2(bbq.x, a2, aq[i][0]);
                aq[i][1] = ffma2(bbq.y, a2, aq[i][1]);
                ak[i][0] = ffma2(bbk.x, a2, ak[i][0]);
                ak[i][1] = ffma2(bbk.y, a2, ak[i][1]);
            }
        }
        __syncthreads();
    }
    float4 bq4 = *(const float4*)(bq + tx * TN);
    float4 bk4 = *(const float4*)(bk + tx * TN);
#pragma unroll
    for (int i = 0; i < TM; i++) {
        int m = m0 + ty * TM + i;
        float v0, v1, v2, v3;
        // q output (plain layout)
        unpack2(aq[i][0], v0, v1);
        unpack2(aq[i][1], v2, v3);
        float4 o;
        o.x = v0 + bq4.x; o.y = v1 + bq4.y; o.z = v2 + bq4.z; o.w = v3 + bq4.w;
        *(float4*)(Yq + (size_t)m * DDIM + tx * TN) = o;
        // k output: hi/lo split into KT tile layout
        float kv[4];
        unpack2(ak[i][0], kv[0], kv[1]);
        unpack2(ak[i][1], kv[2], kv[3]);
        kv[0] += bk4.x; kv[1] += bk4.y; kv[2] += bk4.z; kv[3] += bk4.w;
        int key = m & 63;
        size_t base = (size_t)(m >> 6) * 2048;
#pragma unroll
        for (int j = 0; j < 4; j++) {
            int d = tx * 4 + j;
            float hi = trunc13(kv[j]);
            float lo = __uint_as_float(to_tf32(kv[j] - hi));
            size_t w = base + (size_t)(d * 64 + (key ^ ((d & 3) * 8)));
            KTH[w] = hi;
            KTL[w] = lo;
        }
    }
}

// ============================================================================
// V projection GEMM (round-2, passing)
// ============================================================================
template<int BM, int BN, int BK, int TM, int TN>
__global__ void sgemm_bias_kernel(const float* __restrict__ A, const float* __restrict__ W,
                                  const float* __restrict__ bias, float* __restrict__ Y,
                                  int M, int Kd, int N) {
    __shared__ float As[BK][BM + 4];
    __shared__ float Bs[BK][BN];
    constexpr int TX = BN / TN;
    constexpr int NT = (BM / TM) * TX;
    const int tid = threadIdx.x;
    const int tx = tid % TX, ty = tid / TX;
    const int m0 = blockIdx.x * BM, n0 = blockIdx.y * BN;

    unsigned long long acc[TM][2];
#pragma unroll
    for (int i = 0; i < TM; i++) { acc[i][0] = 0ull; acc[i][1] = 0ull; }

    for (int k0 = 0; k0 < Kd; k0 += BK) {
        for (int idx = tid; idx < BM * BK / 4; idx += NT) {
            int m = idx / (BK / 4), kq = idx % (BK / 4);
            float4 t4 = *(const float4*)(A + (size_t)(m0 + m) * Kd + k0 + kq * 4);
            As[kq * 4 + 0][m] = t4.x; As[kq * 4 + 1][m] = t4.y;
            As[kq * 4 + 2][m] = t4.z; As[kq * 4 + 3][m] = t4.w;
        }
        for (int idx = tid; idx < BK * BN / 4; idx += NT) {
            int kk = idx / (BN / 4), nq = idx % (BN / 4);
            *(float4*)&Bs[kk][nq * 4] = *(const float4*)(W + (size_t)(k0 + kk) * N + n0 + nq * 4);
        }
        __syncthreads();
#pragma unroll
        for (int kk = 0; kk < BK; kk++) {
            ulonglong2 bb = *(const ulonglong2*)&Bs[kk][tx * TN];
#pragma unroll
            for (int i = 0; i < TM; i++) {
                float a = As[kk][ty * TM + i];
                unsigned long long a2 = pack2(a, a);
                acc[i][0] = ffma2(bb.x, a2, acc[i][0]);
                acc[i][1] = ffma2(bb.y, a2, acc[i][1]);
            }
        }
        __syncthreads();
    }
    float4 bv4 = *(const float4*)(bias + n0 + tx * TN);
#pragma unroll
    for (int i = 0; i < TM; i++) {
        int m = m0 + ty * TM + i;
        float v0, v1, v2, v3;
        unpack2(acc[i][0], v0, v1);
        unpack2(acc[i][1], v2, v3);
        float4 o;
        o.x = v0 + bv4.x; o.y = v1 + bv4.y; o.z = v2 + bv4.z; o.w = v3 + bv4.w;
        *(float4*)(Y + (size_t)m * N + n0 + tx * TN) = o;
    }
}

// ============================================================================
extern "C" void kernel_launch(void* const* d_in, const int* in_sizes, int n_in,
                              void* d_out, int out_size) {
    const float* x  = (const float*)d_in[0];
    const float* wq = (const float*)d_in[1];
    const float* bq = (const float*)d_in[2];
    const float* wk = (const float*)d_in[3];
    const float* bk = (const float*)d_in[4];
    const float* wv = (const float*)d_in[5];
    const float* bv = (const float*)d_in[6];
    float* out = (float*)d_out;

    float *qp, *kthp, *ktlp, *vp;
    cudaGetSymbolAddress((void**)&qp, g_q);
    cudaGetSymbolAddress((void**)&kthp, g_kth);
    cudaGetSymbolAddress((void**)&ktlp, g_ktl);
    cudaGetSymbolAddress((void**)&vp, g_v);

    {
        dim3 g(BATCH * SEQ / 64, 1);
        sgemm_qk<<<g, 256>>>(x, wq, bq, wk, bk, qp, kthp, ktlp);
    }
    {
        dim3 g(BATCH * SEQ / 128, CDIM / 64);
        sgemm_bias_kernel<128, 64, 16, 8, 4><<<g, 256>>>(x, wv, bv, vp, BATCH * SEQ, CDIM, CDIM);
    }
    {
        cudaFuncSetAttribute(flash_mma, cudaFuncAttributeMaxDynamicSharedMemorySize, FLASH_SMEM);
        dim3 g(SEQ / TQ, BATCH);
        flash_mma<<<g, 256, FLASH_SMEM>>>(qp, kthp, ktlp, vp, x, out);
    }
}

// round 11
// speedup vs baseline: 1.4717x; 1.0988x over previous
#include <cuda_runtime.h>
#include <cstdint>

#define BATCH 4
#define SEQ   4096
#define CDIM  256
#define DDIM  32
#define TQ    128
#define TK    64
#define NT_TILES (SEQ / TK)
#define LOG2E 1.4426950408889634f

// ---- scratch ----
__device__ float g_q[BATCH * SEQ * DDIM];
__device__ float g_kth[BATCH * (SEQ / TK) * 32 * 64];   // K-hi, KT tile layout
__device__ float g_ktl[BATCH * (SEQ / TK) * 32 * 64];   // K-lo, KT tile layout
__device__ float g_v[BATCH * SEQ * CDIM];

// ---- helpers ----
__device__ __forceinline__ unsigned long long pack2(float lo, float hi) {
    unsigned long long r;
    asm("mov.b64 %0, {%1, %2};" : "=l"(r) : "f"(lo), "f"(hi));
    return r;
}
__device__ __forceinline__ void unpack2(unsigned long long v, float& lo, float& hi) {
    asm("mov.b64 {%0, %1}, %2;" : "=f"(lo), "=f"(hi) : "l"(v));
}
__device__ __forceinline__ unsigned long long ffma2(unsigned long long a, unsigned long long b,
                                                    unsigned long long c) {
    unsigned long long d;
    asm("fma.rn.f32x2 %0, %1, %2, %3;" : "=l"(d) : "l"(a), "l"(b), "l"(c));
    return d;
}
__device__ __forceinline__ uint32_t smem_u32(const void* p) {
    uint32_t a;
    asm("{ .reg .u64 t; cvta.to.shared.u64 t, %1; cvt.u32.u64 %0, t; }" : "=r"(a) : "l"(p));
    return a;
}
__device__ __forceinline__ void cp_async16(uint32_t dst, const void* src) {
    asm volatile("cp.async.cg.shared.global [%0], [%1], 16;" :: "r"(dst), "l"(src));
}
__device__ __forceinline__ uint32_t to_tf32(float f) {
    uint32_t u;
    asm("cvt.rna.tf32.f32 %0, %1;" : "=r"(u) : "f"(f));
    return u;
}
__device__ __forceinline__ float trunc13(float x) {
    return __uint_as_float(__float_as_uint(x) & 0xFFFFE000u);
}
__device__ __forceinline__ float ex2(float x) {
    float r;
    asm("ex2.approx.f32 %0, %1;" : "=f"(r) : "f"(x));
    return r;
}
__device__ __forceinline__ void mma8(float d[4], uint32_t a0, uint32_t a1, uint32_t a2,
                                     uint32_t a3, uint32_t b0, uint32_t b1) {
    asm volatile(
        "mma.sync.aligned.m16n8k8.row.col.f32.tf32.tf32.f32 "
        "{%0,%1,%2,%3}, {%4,%5,%6,%7}, {%8,%9}, {%0,%1,%2,%3};"
        : "+f"(d[0]), "+f"(d[1]), "+f"(d[2]), "+f"(d[3])
        : "r"(a0), "r"(a1), "r"(a2), "r"(a3), "r"(b0), "r"(b1));
}

// ---- smem byte offsets (flash; round-5 layout, proven) ----
#define OFF_QHI 0
#define OFF_QLO 16384
#define OFF_KTH 32768
#define OFF_KTL 40960
#define OFF_P   49152
#define OFF_V   81920       /* 2 x 65536 */
#define OFF_L   212992
#define OFF_LP  213504
#define FLASH_SMEM 215552

// round-5 word-index swizzles (proven)
__device__ __forceinline__ int pQ(int r, int d)  { return r * 32 + (d ^ ((r & 7) * 4)); }
__device__ __forceinline__ int pKT(int d, int k) { return d * 64 + (k ^ ((d & 3) * 8)); }
__device__ __forceinline__ int pP(int r, int c)  { return r * 64 + (c ^ ((r & 7) * 4)); }
__device__ __forceinline__ int pV(int k, int n)  { return k * 256 + (n ^ ((k & 3) * 8)); }

// ============================================================================
// Flash attention on mma.sync tf32 (round-10, passing at 381 us)
// ============================================================================
__global__ __launch_bounds__(256, 1)
void flash_mma(const float* __restrict__ Qg,
               const float* __restrict__ KTHg, const float* __restrict__ KTLg,
               const float* __restrict__ Vg, const float* __restrict__ X,
               float* __restrict__ Out) {
    extern __shared__ char smem[];
    float*    sQh  = (float*)(smem + OFF_QHI);
    float*    sQl  = (float*)(smem + OFF_QLO);
    float*    sKTh = (float*)(smem + OFF_KTH);
    float*    sKTl = (float*)(smem + OFF_KTL);
    uint32_t* sPu  = (uint32_t*)(smem + OFF_P);
    uint32_t* sVu  = (uint32_t*)(smem + OFF_V);
    float*    sL   = (float*)(smem + OFF_L);
    float*    sLp  = (float*)(smem + OFF_LP);
    const uint32_t sb = smem_u32(smem);

    const int tid  = threadIdx.x;
    const int lane = tid & 31;
    const int wid  = tid >> 5;
    const int mw   = wid & 1;
    const int nw   = wid >> 1;
    const int g    = lane >> 2;
    const int l4   = lane & 3;
    const int b    = blockIdx.y;
    const int q0   = blockIdx.x * TQ;

    const float* Qb = Qg + ((size_t)b * SEQ + q0) * DDIM;
    const char*  KThb = (const char*)(KTHg + (size_t)b * NT_TILES * 2048);
    const char*  KTlb = (const char*)(KTLg + (size_t)b * NT_TILES * 2048);
    const float* Vb = Vg + (size_t)b * SEQ * CDIM;

    // ---- prologue ----
    if (tid < 128) sL[tid] = 0.0f;
#pragma unroll
    for (int i = 0; i < 4; i++) {
        int idx = tid + i * 256;
        int r = idx >> 3, d4 = idx & 7;
        float4 v = *(const float4*)(Qb + r * DDIM + d4 * 4);
        v.x *= LOG2E; v.y *= LOG2E; v.z *= LOG2E; v.w *= LOG2E;
        float4 hi, lo;
        hi.x = trunc13(v.x); lo.x = __uint_as_float(to_tf32(v.x - hi.x));
        hi.y = trunc13(v.y); lo.y = __uint_as_float(to_tf32(v.y - hi.y));
        hi.z = trunc13(v.z); lo.z = __uint_as_float(to_tf32(v.z - hi.z));
        hi.w = trunc13(v.w); lo.w = __uint_as_float(to_tf32(v.w - hi.w));
        int base = r * 32 + ((d4 * 4) ^ ((r & 7) * 4));
        *(float4*)(sQh + base) = hi;
        *(float4*)(sQl + base) = lo;
    }
#pragma unroll
    for (int i = 0; i < 2; i++) {
        uint32_t off = (uint32_t)(tid + i * 256) * 16u;
        cp_async16(sb + OFF_KTH + off, KThb + off);
        cp_async16(sb + OFF_KTL + off, KTlb + off);
    }
#pragma unroll
    for (int i = 0; i < 16; i++) {
        int f = tid + i * 256;
        int key = f >> 6, n4 = f & 63;
        uint32_t dst = sb + OFF_V + (uint32_t)pV(key, n4 * 4) * 4u;
        cp_async16(dst, Vb + (size_t)key * CDIM + n4 * 4);
    }
    asm volatile("cp.async.commit_group;" ::: "memory");
    asm volatile("cp.async.wait_group 0;" ::: "memory");
    __syncthreads();

    float oa[4][8][4];
#pragma unroll
    for (int mt = 0; mt < 4; mt++)
#pragma unroll
        for (int nt = 0; nt < 8; nt++)
#pragma unroll
            for (int c = 0; c < 4; c++) oa[mt][nt][c] = 0.0f;

#pragma unroll 1
    for (int t = 0; t < NT_TILES; t++) {
        const int buf = t & 1;
        const bool have_next = (t + 1 < NT_TILES);

        if (have_next) {
            const float* Vs = Vb + (size_t)(t + 1) * TK * CDIM;
            uint32_t vb0 = sb + OFF_V + (uint32_t)(1 - buf) * 65536u;
#pragma unroll
            for (int i = 0; i < 16; i++) {
                int f = tid + i * 256;
                int key = f >> 6, n4 = f & 63;
                cp_async16(vb0 + (uint32_t)pV(key, n4 * 4) * 4u, Vs + (size_t)key * CDIM + n4 * 4);
            }
            asm volatile("cp.async.commit_group;" ::: "memory");
        }

        float sa[4][2][4];
#pragma unroll
        for (int mt = 0; mt < 4; mt++)
#pragma unroll
            for (int nt = 0; nt < 2; nt++)
#pragma unroll
                for (int c = 0; c < 4; c++) sa[mt][nt][c] = 0.0f;

#pragma unroll
        for (int ks = 0; ks < 4; ks++) {
            const int k0 = ks * 8;
            uint32_t bh[2][2], bl[2][2];
#pragma unroll
            for (int nt = 0; nt < 2; nt++) {
                int key = nw * 16 + nt * 8 + g;
                int i0 = pKT(k0 + l4, key), i1 = pKT(k0 + 4 + l4, key);
                bh[nt][0] = __float_as_uint(sKTh[i0]);
                bh[nt][1] = __float_as_uint(sKTh[i1]);
                bl[nt][0] = __float_as_uint(sKTl[i0]);
                bl[nt][1] = __float_as_uint(sKTl[i1]);
            }
#pragma unroll
            for (int mt = 0; mt < 4; mt++) {
                int r0 = mw * 64 + mt * 16 + g;
                uint32_t ah0 = __float_as_uint(sQh[pQ(r0, k0 + l4)]);
                uint32_t ah1 = __float_as_uint(sQh[pQ(r0 + 8, k0 + l4)]);
                uint32_t ah2 = __float_as_uint(sQh[pQ(r0, k0 + 4 + l4)]);
                uint32_t ah3 = __float_as_uint(sQh[pQ(r0 + 8, k0 + 4 + l4)]);
                uint32_t al0 = __float_as_uint(sQl[pQ(r0, k0 + l4)]);
                uint32_t al1 = __float_as_uint(sQl[pQ(r0 + 8, k0 + l4)]);
                uint32_t al2 = __float_as_uint(sQl[pQ(r0, k0 + 4 + l4)]);
                uint32_t al3 = __float_as_uint(sQl[pQ(r0 + 8, k0 + 4 + l4)]);
#pragma unroll
                for (int nt = 0; nt < 2; nt++) {
                    mma8(sa[mt][nt], ah0, ah1, ah2, ah3, bh[nt][0], bh[nt][1]);
                    mma8(sa[mt][nt], ah0, ah1, ah2, ah3, bl[nt][0], bl[nt][1]);
                    mma8(sa[mt][nt], al0, al1, al2, al3, bh[nt][0], bh[nt][1]);
                }
            }
        }

#pragma unroll
        for (int mt = 0; mt < 4; mt++) {
            int r0 = mw * 64 + mt * 16 + g;
            float s0 = 0.0f, s1 = 0.0f;
#pragma unroll
            for (int nt = 0; nt < 2; nt++) {
                int col = nw * 16 + nt * 8 + l4 * 2;
                uint32_t e0 = __float_as_uint(ex2(sa[mt][nt][0])) & 0xFFFFE000u;
                uint32_t e1 = __float_as_uint(ex2(sa[mt][nt][1])) & 0xFFFFE000u;
                uint32_t e2 = __float_as_uint(ex2(sa[mt][nt][2])) & 0xFFFFE000u;
                uint32_t e3 = __float_as_uint(ex2(sa[mt][nt][3])) & 0xFFFFE000u;
                s0 += __uint_as_float(e0) + __uint_as_float(e1);
                s1 += __uint_as_float(e2) + __uint_as_float(e3);
                uint2 w0; w0.x = e0; w0.y = e1;
                uint2 w1; w1.x = e2; w1.y = e3;
                *(uint2*)(sPu + pP(r0, col)) = w0;
                *(uint2*)(sPu + pP(r0 + 8, col)) = w1;
            }
            s0 += __shfl_xor_sync(0xffffffffu, s0, 1);
            s0 += __shfl_xor_sync(0xffffffffu, s0, 2);
            s1 += __shfl_xor_sync(0xffffffffu, s1, 1);
            s1 += __shfl_xor_sync(0xffffffffu, s1, 2);
            if (l4 == 0) {
                sLp[nw * 128 + r0] = s0;
                sLp[nw * 128 + r0 + 8] = s1;
            }
        }
        __syncthreads();   // sync1

        if (have_next) {
            const char* kth_t = KThb + (size_t)(t + 1) * 8192;
            const char* ktl_t = KTlb + (size_t)(t + 1) * 8192;
#pragma unroll
            for (int i = 0; i < 2; i++) {
                uint32_t off = (uint32_t)(tid + i * 256) * 16u;
                cp_async16(sb + OFF_KTH + off, kth_t + off);
                cp_async16(sb + OFF_KTL + off, ktl_t + off);
            }
            asm volatile("cp.async.commit_group;" ::: "memory");
        }
        if (tid < 128)
            sL[tid] += (sLp[tid] + sLp[128 + tid]) + (sLp[256 + tid] + sLp[384 + tid]);

        const uint32_t* sVb = sVu + (size_t)buf * 16384;
#pragma unroll
        for (int ks = 0; ks < 8; ks++) {
            const int k0 = ks * 8;
            uint32_t pa[4][4];
#pragma unroll
            for (int mt = 0; mt < 4; mt++) {
                int r0 = mw * 64 + mt * 16 + g;
                pa[mt][0] = sPu[pP(r0, k0 + l4)];
                pa[mt][1] = sPu[pP(r0 + 8, k0 + l4)];
                pa[mt][2] = sPu[pP(r0, k0 + 4 + l4)];
                pa[mt][3] = sPu[pP(r0 + 8, k0 + 4 + l4)];
            }
#pragma unroll
            for (int nt = 0; nt < 8; nt++) {
                int n = nw * 64 + nt * 8 + g;
                uint32_t b0 = sVb[pV(k0 + l4, n)];
                uint32_t b1 = sVb[pV(k0 + 4 + l4, n)];
#pragma unroll
                for (int mt = 0; mt < 4; mt++)
                    mma8(oa[mt][nt], pa[mt][0], pa[mt][1], pa[mt][2], pa[mt][3], b0, b1);
            }
        }

        asm volatile("cp.async.wait_group 0;" ::: "memory");
        __syncthreads();   // sync2
    }

    // ---- epilogue: O/l + residual ----
#pragma unroll
    for (int mt = 0; mt < 4; mt++) {
        int r0 = mw * 64 + mt * 16 + g;
        float inv0 = 1.0f / sL[r0];
        float inv1 = 1.0f / sL[r0 + 8];
        size_t row0 = (size_t)b * SEQ + q0 + r0;
#pragma unroll
        for (int nt = 0; nt < 8; nt++) {
            int col = nw * 64 + nt * 8 + l4 * 2;
            const float2* x0 = (const float2*)(X + (row0)*CDIM + col);
            const float2* x1 = (const float2*)(X + (row0 + 8) * CDIM + col);
            float2 xv0 = *x0, xv1 = *x1;
            float2 o0, o1;
            o0.x = oa[mt][nt][0] * inv0 + xv0.x;
            o0.y = oa[mt][nt][1] * inv0 + xv0.y;
            o1.x = oa[mt][nt][2] * inv1 + xv1.x;
            o1.y = oa[mt][nt][3] * inv1 + xv1.y;
            *(float2*)(Out + (row0)*CDIM + col) = o0;
            *(float2*)(Out + (row0 + 8) * CDIM + col) = o1;
        }
    }
}

// ============================================================================
// Merged q+k projection (round-10, 256 threads)
// ============================================================================
__global__ __launch_bounds__(256)
void sgemm_qk(const float* __restrict__ A,
              const float* __restrict__ Wq, const float* __restrict__ bq,
              const float* __restrict__ Wk, const float* __restrict__ bk,
              float* __restrict__ Yq, float* __restrict__ KTH, float* __restrict__ KTL) {
    constexpr int BM = 64, BK = 16, BN = 32, TM = 2, TN = 4, TX = 8;
    __shared__ float As[BK][BM + 4];
    __shared__ float Bq[BK][BN];
    __shared__ float Bk[BK][BN];
    const int tid = threadIdx.x;
    const int tx = tid % TX, ty = tid / TX;
    const int m0 = blockIdx.x * BM;

    unsigned long long aq[TM][2], ak[TM][2];
#pragma unroll
    for (int i = 0; i < TM; i++) {
        aq[i][0] = aq[i][1] = 0ull;
        ak[i][0] = ak[i][1] = 0ull;
    }

    for (int k0 = 0; k0 < CDIM; k0 += BK) {
        {
            int m = tid >> 2, kq = tid & 3;
            float4 t4 = *(const float4*)(A + (size_t)(m0 + m) * CDIM + k0 + kq * 4);
            As[kq * 4 + 0][m] = t4.x; As[kq * 4 + 1][m] = t4.y;
            As[kq * 4 + 2][m] = t4.z; As[kq * 4 + 3][m] = t4.w;
        }
        if (tid < 128) {
            int kk = tid >> 3, nq = tid & 7;
            *(float4*)&Bq[kk][nq * 4] = *(const float4*)(Wq + (size_t)(k0 + kk) * DDIM + nq * 4);
            *(float4*)&Bk[kk][nq * 4] = *(const float4*)(Wk + (size_t)(k0 + kk) * DDIM + nq * 4);
        }
        __syncthreads();
#pragma unroll
        for (int kk = 0; kk < BK; kk++) {
            ulonglong2 bbq = *(const ulonglong2*)&Bq[kk][tx * TN];
            ulonglong2 bbk = *(const ulonglong2*)&Bk[kk][tx * TN];
#pragma unroll
            for (int i = 0; i < TM; i++) {
                float a = As[kk][ty * TM + i];
                unsigned long long a2 = pack2(a, a);
                aq[i][0] = ffma2(bbq.x, a2, aq[i][0]);
                aq[i][1] = ffma2(bbq.y, a2, aq[i][1]);
                ak[i][0] = ffma2(bbk.x, a2, ak[i][0]);
                ak[i][1] = ffma2(bbk.y, a2, ak[i][1]);
            }
        }
        __syncthreads();
    }
    float4 bq4 = *(const float4*)(bq + tx * TN);
    float4 bk4 = *(const float4*)(bk + tx * TN);
#pragma unroll
    for (int i = 0; i < TM; i++) {
        int m = m0 + ty * TM + i;
        float v0, v1, v2, v3;
        unpack2(aq[i][0], v0, v1);
        unpack2(aq[i][1], v2, v3);
        float4 o;
        o.x = v0 + bq4.x; o.y = v1 + bq4.y; o.z = v2 + bq4.z; o.w = v3 + bq4.w;
        *(float4*)(Yq + (size_t)m * DDIM + tx * TN) = o;
        float kv[4];
        unpack2(ak[i][0], kv[0], kv[1]);
        unpack2(ak[i][1], kv[2], kv[3]);
        kv[0] += bk4.x; kv[1] += bk4.y; kv[2] += bk4.z; kv[3] += bk4.w;
        int key = m & 63;
        size_t base = (size_t)(m >> 6) * 2048;
#pragma unroll
        for (int j = 0; j < 4; j++) {
            int d = tx * 4 + j;
            float hi = trunc13(kv[j]);
            float lo = __uint_as_float(to_tf32(kv[j] - hi));
            size_t w = base + (size_t)(d * 64 + (key ^ ((d & 3) * 8)));
            KTH[w] = hi;
            KTL[w] = lo;
        }
    }
}

// ============================================================================
// V projection on mma.sync tf32 (single-term: consumer truncates V anyway).
// C[16384,256] = X @ Wv + bv. BM=128, BN=128, BK=32 double-buffered cp.async.
// 256 threads = 8 warps (2 row-halves x 4 col-groups).
// ============================================================================
#define VP_SMEM (4 * 16384)   /* A:2x16KB + B:2x16KB */
__device__ __forceinline__ int pA8(int r, int k) { return r * 32 + (k ^ ((r & 7) * 4)); }
__device__ __forceinline__ int pB8(int k, int n) { return k * 128 + (n ^ ((k & 3) * 8)); }

__global__ __launch_bounds__(256, 2)
void sgemm_v_mma(const float* __restrict__ Xg, const float* __restrict__ Wv,
                 const float* __restrict__ bv, float* __restrict__ Vout) {
    extern __shared__ char smem[];
    float* sA = (float*)smem;                   // 2 x [128][32]
    float* sB = (float*)(smem + 32768);         // 2 x [32][128]
    const uint32_t sb = smem_u32(smem);

    const int tid  = threadIdx.x;
    const int lane = tid & 31;
    const int wid  = tid >> 5;
    const int mw   = wid & 1;
    const int nw   = wid >> 1;
    const int g    = lane >> 2;
    const int l4   = lane & 3;
    const int m0   = blockIdx.x * 128;
    const int n0   = blockIdx.y * 128;

    float acc[4][4][4];
#pragma unroll
    for (int mt = 0; mt < 4; mt++)
#pragma unroll
        for (int nt = 0; nt < 4; nt++)
#pragma unroll
            for (int c = 0; c < 4; c++) acc[mt][nt][c] = 0.0f;

    // async loaders: A tile 1024 f4 (4/thread), B tile 1024 f4 (4/thread)
    auto load_tiles = [&](int k0, int bufsel) {
        uint32_t abase = sb + (uint32_t)bufsel * 16384u;
        uint32_t bbase = sb + 32768u + (uint32_t)bufsel * 16384u;
#pragma unroll
        for (int i = 0; i < 4; i++) {
            int idx = tid + i * 256;
            int r = idx >> 3, c4 = idx & 7;
            uint32_t dst = abase + (uint32_t)(r * 32 + ((c4 * 4) ^ ((r & 7) * 4))) * 4u;
            cp_async16(dst, Xg + (size_t)(m0 + r) * CDIM + k0 + c4 * 4);
        }
#pragma unroll
        for (int i = 0; i < 4; i++) {
            int idx = tid + i * 256;
            int k = idx >> 5, n4 = idx & 31;
            uint32_t dst = bbase + (uint32_t)(k * 128 + ((n4 * 4) ^ ((k & 3) * 8))) * 4u;
            cp_async16(dst, Wv + (size_t)(k0 + k) * CDIM + n0 + n4 * 4);
        }
        asm volatile("cp.async.commit_group;" ::: "memory");
    };

    load_tiles(0, 0);

#pragma unroll 1
    for (int t = 0; t < 8; t++) {
        const int buf = t & 1;
        const bool have_next = (t + 1 < 8);
        if (have_next) load_tiles((t + 1) * 32, 1 - buf);
        if (have_next) asm volatile("cp.async.wait_group 1;" ::: "memory");
        else           asm volatile("cp.async.wait_group 0;" ::: "memory");
        __syncthreads();

        const float* A = sA + (size_t)buf * 4096;
        const float* B = sB + (size_t)buf * 4096;
#pragma unroll
        for (int ks = 0; ks < 4; ks++) {
            const int k8 = ks * 8;
            uint32_t bfr[4][2];
#pragma unroll
            for (int nt = 0; nt < 4; nt++) {
                int n = nw * 32 + nt * 8 + g;
                bfr[nt][0] = __float_as_uint(B[pB8(k8 + l4, n)]);
                bfr[nt][1] = __float_as_uint(B[pB8(k8 + 4 + l4, n)]);
            }
#pragma unroll
            for (int mt = 0; mt < 4; mt++) {
                int r0 = mw * 64 + mt * 16 + g;
                uint32_t a0 = __float_as_uint(A[pA8(r0, k8 + l4)]);
                uint32_t a1 = __float_as_uint(A[pA8(r0 + 8, k8 + l4)]);
                uint32_t a2 = __float_as_uint(A[pA8(r0, k8 + 4 + l4)]);
                uint32_t a3 = __float_as_uint(A[pA8(r0 + 8, k8 + 4 + l4)]);
#pragma unroll
                for (int nt = 0; nt < 4; nt++)
                    mma8(acc[mt][nt], a0, a1, a2, a3, bfr[nt][0], bfr[nt][1]);
            }
        }
        __syncthreads();
    }

    // epilogue: + bias, store fp32
#pragma unroll
    for (int mt = 0; mt < 4; mt++) {
        int r0 = m0 + mw * 64 + mt * 16 + g;
#pragma unroll
        for (int nt = 0; nt < 4; nt++) {
            int col = n0 + nw * 32 + nt * 8 + l4 * 2;
            float2 bb = *(const float2*)(bv + col);
            float2 o0, o1;
            o0.x = acc[mt][nt][0] + bb.x;
            o0.y = acc[mt][nt][1] + bb.y;
            o1.x = acc[mt][nt][2] + bb.x;
            o1.y = acc[mt][nt][3] + bb.y;
            *(float2*)(Vout + (size_t)r0 * CDIM + col) = o0;
            *(float2*)(Vout + (size_t)(r0 + 8) * CDIM + col) = o1;
        }
    }
}

// ============================================================================
extern "C" void kernel_launch(void* const* d_in, const int* in_sizes, int n_in,
                              void* d_out, int out_size) {
    const float* x  = (const float*)d_in[0];
    const float* wq = (const float*)d_in[1];
    const float* bq = (const float*)d_in[2];
    const float* wk = (const float*)d_in[3];
    const float* bk = (const float*)d_in[4];
    const float* wv = (const float*)d_in[5];
    const float* bv = (const float*)d_in[6];
    float* out = (float*)d_out;

    float *qp, *kthp, *ktlp, *vp;
    cudaGetSymbolAddress((void**)&qp, g_q);
    cudaGetSymbolAddress((void**)&kthp, g_kth);
    cudaGetSymbolAddress((void**)&ktlp, g_ktl);
    cudaGetSymbolAddress((void**)&vp, g_v);

    {
        dim3 g(BATCH * SEQ / 64, 1);
        sgemm_qk<<<g, 256>>>(x, wq, bq, wk, bk, qp, kthp, ktlp);
    }
    {
        cudaFuncSetAttribute(sgemm_v_mma, cudaFuncAttributeMaxDynamicSharedMemorySize, VP_SMEM);
        dim3 g(BATCH * SEQ / 128, CDIM / 128);
        sgemm_v_mma<<<g, 256, VP_SMEM>>>(x, wv, bv, vp);
    }
    {
        cudaFuncSetAttribute(flash_mma, cudaFuncAttributeMaxDynamicSharedMemorySize, FLASH_SMEM);
        dim3 g(SEQ / TQ, BATCH);
        flash_mma<<<g, 256, FLASH_SMEM>>>(qp, kthp, ktlp, vp, x, out);
    }
}

// round 12
// speedup vs baseline: 1.6793x; 1.1411x over previous
#include <cuda_runtime.h>
#include <cstdint>

#define BATCH 4
#define SEQ   4096
#define CDIM  256
#define DDIM  32
#define TQ    128
#define TK    64
#define NT_TILES (SEQ / TK)
#define LOG2E 1.4426950408889634f

// ---- scratch ----
__device__ float g_q[BATCH * SEQ * DDIM];
__device__ float g_kth[BATCH * NT_TILES * 1024];   // K-hi bf16x2 words, KT tile layout
__device__ float g_ktl[BATCH * NT_TILES * 1024];   // K-lo bf16x2 words
__device__ float g_v[BATCH * SEQ * CDIM];

// ---- helpers ----
__device__ __forceinline__ unsigned long long pack2(float lo, float hi) {
    unsigned long long r;
    asm("mov.b64 %0, {%1, %2};" : "=l"(r) : "f"(lo), "f"(hi));
    return r;
}
__device__ __forceinline__ void unpack2(unsigned long long v, float& lo, float& hi) {
    asm("mov.b64 {%0, %1}, %2;" : "=f"(lo), "=f"(hi) : "l"(v));
}
__device__ __forceinline__ unsigned long long ffma2(unsigned long long a, unsigned long long b,
                                                    unsigned long long c) {
    unsigned long long d;
    asm("fma.rn.f32x2 %0, %1, %2, %3;" : "=l"(d) : "l"(a), "l"(b), "l"(c));
    return d;
}
__device__ __forceinline__ uint32_t smem_u32(const void* p) {
    uint32_t a;
    asm("{ .reg .u64 t; cvta.to.shared.u64 t, %1; cvt.u32.u64 %0, t; }" : "=r"(a) : "l"(p));
    return a;
}
__device__ __forceinline__ void cp_async16(uint32_t dst, const void* src) {
    asm volatile("cp.async.cg.shared.global [%0], [%1], 16;" :: "r"(dst), "l"(src));
}
__device__ __forceinline__ float ex2(float x) {
    float r;
    asm("ex2.approx.f32 %0, %1;" : "=f"(r) : "f"(x));
    return r;
}
// bf16x2 pack: lower half = lo, upper half = hi (PTX: second src -> lower)
__device__ __forceinline__ uint32_t bfpack(float lo, float hi) {
    uint32_t r;
    asm("cvt.rn.bf16x2.f32 %0, %1, %2;" : "=r"(r) : "f"(hi), "f"(lo));
    return r;
}
// truncate-to-bf16 pack of two floats: lower = x0 top bits, upper = x1 top bits
__device__ __forceinline__ uint32_t bftruncpack(float x0, float x1) {
    return __byte_perm(__float_as_uint(x0), __float_as_uint(x1), 0x7632);
}
__device__ __forceinline__ float bftrunc_res(float x) {
    return x - __uint_as_float(__float_as_uint(x) & 0xFFFF0000u);
}
// tf32 mma m16n8k8
__device__ __forceinline__ void mma8(float d[4], uint32_t a0, uint32_t a1, uint32_t a2,
                                     uint32_t a3, uint32_t b0, uint32_t b1) {
    asm volatile(
        "mma.sync.aligned.m16n8k8.row.col.f32.tf32.tf32.f32 "
        "{%0,%1,%2,%3}, {%4,%5,%6,%7}, {%8,%9}, {%0,%1,%2,%3};"
        : "+f"(d[0]), "+f"(d[1]), "+f"(d[2]), "+f"(d[3])
        : "r"(a0), "r"(a1), "r"(a2), "r"(a3), "r"(b0), "r"(b1));
}
// bf16 mma m16n8k16
__device__ __forceinline__ void mma16(float d[4], uint32_t a0, uint32_t a1, uint32_t a2,
                                      uint32_t a3, uint32_t b0, uint32_t b1) {
    asm volatile(
        "mma.sync.aligned.m16n8k16.row.col.f32.bf16.bf16.f32 "
        "{%0,%1,%2,%3}, {%4,%5,%6,%7}, {%8,%9}, {%0,%1,%2,%3};"
        : "+f"(d[0]), "+f"(d[1]), "+f"(d[2]), "+f"(d[3])
        : "r"(a0), "r"(a1), "r"(a2), "r"(a3), "r"(b0), "r"(b1));
}

// ---- flash smem byte offsets ----
#define OFF_QH16 0          /* 8 KB : 128 rows x 16 bf16x2 words */
#define OFF_QL16 8192       /* 8 KB */
#define OFF_KTH  16384      /* 4 KB : 64 keys x 16 bf16x2 words */
#define OFF_KTL  20480      /* 4 KB */
#define OFF_P    24576      /* 32 KB */
#define OFF_V    57344      /* 2 x 64 KB */
#define OFF_L    188416     /* 512 B */
#define OFF_LP   188928     /* 2 KB */
#define FLASH_SMEM 190976

// word-index swizzles
__device__ __forceinline__ int pQ16(int r, int w)   { return r * 16 + (w ^ ((r & 7) * 2)); }
__device__ __forceinline__ int pK16(int key, int w) { return key * 16 + (w ^ ((key & 7) * 2)); }
__device__ __forceinline__ int pP(int r, int c)     { return r * 64 + (c ^ ((r & 7) * 4)); }
__device__ __forceinline__ int pV(int k, int n)     { return k * 256 + (n ^ ((k & 3) * 8)); }

// ============================================================================
// Flash attention: QK on bf16 3-term mma, PV on tf32 mma (round-10 structure).
// 256 threads = 8 warps: mw = wid&1 (64 rows), nw = wid>>1 (16 keys / 64 PV cols)
// ============================================================================
__global__ __launch_bounds__(256, 1)
void flash_mma(const float* __restrict__ Qg,
               const float* __restrict__ KTHg, const float* __restrict__ KTLg,
               const float* __restrict__ Vg, const float* __restrict__ X,
               float* __restrict__ Out) {
    extern __shared__ char smem[];
    uint32_t* sQh = (uint32_t*)(smem + OFF_QH16);
    uint32_t* sQl = (uint32_t*)(smem + OFF_QL16);
    uint32_t* sKh = (uint32_t*)(smem + OFF_KTH);
    uint32_t* sKl = (uint32_t*)(smem + OFF_KTL);
    uint32_t* sPu = (uint32_t*)(smem + OFF_P);
    uint32_t* sVu = (uint32_t*)(smem + OFF_V);
    float*    sL  = (float*)(smem + OFF_L);
    float*    sLp = (float*)(smem + OFF_LP);
    const uint32_t sb = smem_u32(smem);

    const int tid  = threadIdx.x;
    const int lane = tid & 31;
    const int wid  = tid >> 5;
    const int mw   = wid & 1;
    const int nw   = wid >> 1;
    const int g    = lane >> 2;
    const int l4   = lane & 3;
    const int b    = blockIdx.y;
    const int q0   = blockIdx.x * TQ;

    const float* Qb = Qg + ((size_t)b * SEQ + q0) * DDIM;
    const char*  KThb = (const char*)(KTHg + (size_t)b * NT_TILES * 1024);
    const char*  KTlb = (const char*)(KTLg + (size_t)b * NT_TILES * 1024);
    const float* Vb = Vg + (size_t)b * SEQ * CDIM;

    // ---- prologue ----
    if (tid < 128) sL[tid] = 0.0f;
    // Q: scale by log2e, bf16 hi/lo split, pack pairs
#pragma unroll
    for (int i = 0; i < 4; i++) {
        int idx = tid + i * 256;
        int r = idx >> 3, d4 = idx & 7;
        float4 v = *(const float4*)(Qb + r * DDIM + d4 * 4);
        v.x *= LOG2E; v.y *= LOG2E; v.z *= LOG2E; v.w *= LOG2E;
        uint32_t hi0 = bftruncpack(v.x, v.y);
        uint32_t hi1 = bftruncpack(v.z, v.w);
        uint32_t lo0 = bfpack(bftrunc_res(v.x), bftrunc_res(v.y));
        uint32_t lo1 = bfpack(bftrunc_res(v.z), bftrunc_res(v.w));
        sQh[pQ16(r, 2 * d4)]     = hi0;
        sQh[pQ16(r, 2 * d4 + 1)] = hi1;
        sQl[pQ16(r, 2 * d4)]     = lo0;
        sQl[pQ16(r, 2 * d4 + 1)] = lo1;
    }
    // KT(0) + V(0) via cp.async (one group); KT tile = 4KB per matrix
    {
        uint32_t off = (uint32_t)tid * 16u;
        cp_async16(sb + OFF_KTH + off, KThb + off);
        cp_async16(sb + OFF_KTL + off, KTlb + off);
    }
#pragma unroll
    for (int i = 0; i < 16; i++) {
        int f = tid + i * 256;
        int key = f >> 6, n4 = f & 63;
        uint32_t dst = sb + OFF_V + (uint32_t)pV(key, n4 * 4) * 4u;
        cp_async16(dst, Vb + (size_t)key * CDIM + n4 * 4);
    }
    asm volatile("cp.async.commit_group;" ::: "memory");
    asm volatile("cp.async.wait_group 0;" ::: "memory");
    __syncthreads();

    float oa[4][8][4];
#pragma unroll
    for (int mt = 0; mt < 4; mt++)
#pragma unroll
        for (int nt = 0; nt < 8; nt++)
#pragma unroll
            for (int c = 0; c < 4; c++) oa[mt][nt][c] = 0.0f;

#pragma unroll 1
    for (int t = 0; t < NT_TILES; t++) {
        const int buf = t & 1;
        const bool have_next = (t + 1 < NT_TILES);

        if (have_next) {
            const float* Vs = Vb + (size_t)(t + 1) * TK * CDIM;
            uint32_t vb0 = sb + OFF_V + (uint32_t)(1 - buf) * 65536u;
#pragma unroll
            for (int i = 0; i < 16; i++) {
                int f = tid + i * 256;
                int key = f >> 6, n4 = f & 63;
                cp_async16(vb0 + (uint32_t)pV(key, n4 * 4) * 4u, Vs + (size_t)key * CDIM + n4 * 4);
            }
            asm volatile("cp.async.commit_group;" ::: "memory");
        }

        // ---- S = QK^T : bf16 3-term (qh*kh + qh*kl + ql*kh), 2 k16 chunks ----
        float sa[4][2][4];
#pragma unroll
        for (int mt = 0; mt < 4; mt++)
#pragma unroll
            for (int nt = 0; nt < 2; nt++)
#pragma unroll
                for (int c = 0; c < 4; c++) sa[mt][nt][c] = 0.0f;

#pragma unroll
        for (int kc = 0; kc < 2; kc++) {
            const int w0 = kc * 8;
            uint32_t bh[2][2], bl[2][2];
#pragma unroll
            for (int nt = 0; nt < 2; nt++) {
                int key = nw * 16 + nt * 8 + g;
                bh[nt][0] = sKh[pK16(key, w0 + l4)];
                bh[nt][1] = sKh[pK16(key, w0 + 4 + l4)];
                bl[nt][0] = sKl[pK16(key, w0 + l4)];
                bl[nt][1] = sKl[pK16(key, w0 + 4 + l4)];
            }
#pragma unroll
            for (int mt = 0; mt < 4; mt++) {
                int r0 = mw * 64 + mt * 16 + g;
                uint32_t qh0 = sQh[pQ16(r0, w0 + l4)];
                uint32_t qh1 = sQh[pQ16(r0 + 8, w0 + l4)];
                uint32_t qh2 = sQh[pQ16(r0, w0 + 4 + l4)];
                uint32_t qh3 = sQh[pQ16(r0 + 8, w0 + 4 + l4)];
                uint32_t ql0 = sQl[pQ16(r0, w0 + l4)];
                uint32_t ql1 = sQl[pQ16(r0 + 8, w0 + l4)];
                uint32_t ql2 = sQl[pQ16(r0, w0 + 4 + l4)];
                uint32_t ql3 = sQl[pQ16(r0 + 8, w0 + 4 + l4)];
#pragma unroll
                for (int nt = 0; nt < 2; nt++) {
                    mma16(sa[mt][nt], qh0, qh1, qh2, qh3, bh[nt][0], bh[nt][1]);
                    mma16(sa[mt][nt], qh0, qh1, qh2, qh3, bl[nt][0], bl[nt][1]);
                    mma16(sa[mt][nt], ql0, ql1, ql2, ql3, bh[nt][0], bh[nt][1]);
                }
            }
        }

        // ---- p = 2^s, truncate to tf32, STS.64 pairs, partial sums ----
#pragma unroll
        for (int mt = 0; mt < 4; mt++) {
            int r0 = mw * 64 + mt * 16 + g;
            float s0 = 0.0f, s1 = 0.0f;
#pragma unroll
            for (int nt = 0; nt < 2; nt++) {
                int col = nw * 16 + nt * 8 + l4 * 2;
                uint32_t e0 = __float_as_uint(ex2(sa[mt][nt][0])) & 0xFFFFE000u;
                uint32_t e1 = __float_as_uint(ex2(sa[mt][nt][1])) & 0xFFFFE000u;
                uint32_t e2 = __float_as_uint(ex2(sa[mt][nt][2])) & 0xFFFFE000u;
                uint32_t e3 = __float_as_uint(ex2(sa[mt][nt][3])) & 0xFFFFE000u;
                s0 += __uint_as_float(e0) + __uint_as_float(e1);
                s1 += __uint_as_float(e2) + __uint_as_float(e3);
                uint2 w0p; w0p.x = e0; w0p.y = e1;
                uint2 w1p; w1p.x = e2; w1p.y = e3;
                *(uint2*)(sPu + pP(r0, col)) = w0p;
                *(uint2*)(sPu + pP(r0 + 8, col)) = w1p;
            }
            s0 += __shfl_xor_sync(0xffffffffu, s0, 1);
            s0 += __shfl_xor_sync(0xffffffffu, s0, 2);
            s1 += __shfl_xor_sync(0xffffffffu, s1, 1);
            s1 += __shfl_xor_sync(0xffffffffu, s1, 2);
            if (l4 == 0) {
                sLp[nw * 128 + r0] = s0;
                sLp[nw * 128 + r0 + 8] = s1;
            }
        }
        __syncthreads();   // sync1: sP/sLp visible; KT free

        if (have_next) {
            const char* kth_t = KThb + (size_t)(t + 1) * 4096;
            const char* ktl_t = KTlb + (size_t)(t + 1) * 4096;
            uint32_t off = (uint32_t)tid * 16u;
            cp_async16(sb + OFF_KTH + off, kth_t + off);
            cp_async16(sb + OFF_KTL + off, ktl_t + off);
            asm volatile("cp.async.commit_group;" ::: "memory");
        }
        if (tid < 128)
            sL[tid] += (sLp[tid] + sLp[128 + tid]) + (sLp[256 + tid] + sLp[384 + tid]);

        // ---- O += P @ V (tf32) ----
        const uint32_t* sVb = sVu + (size_t)buf * 16384;
#pragma unroll
        for (int ks = 0; ks < 8; ks++) {
            const int k0 = ks * 8;
            uint32_t pa[4][4];
#pragma unroll
            for (int mt = 0; mt < 4; mt++) {
                int r0 = mw * 64 + mt * 16 + g;
                pa[mt][0] = sPu[pP(r0, k0 + l4)];
                pa[mt][1] = sPu[pP(r0 + 8, k0 + l4)];
                pa[mt][2] = sPu[pP(r0, k0 + 4 + l4)];
                pa[mt][3] = sPu[pP(r0 + 8, k0 + 4 + l4)];
            }
#pragma unroll
            for (int nt = 0; nt < 8; nt++) {
                int n = nw * 64 + nt * 8 + g;
                uint32_t b0 = sVb[pV(k0 + l4, n)];
                uint32_t b1 = sVb[pV(k0 + 4 + l4, n)];
#pragma unroll
                for (int mt = 0; mt < 4; mt++)
                    mma8(oa[mt][nt], pa[mt][0], pa[mt][1], pa[mt][2], pa[mt][3], b0, b1);
            }
        }

        asm volatile("cp.async.wait_group 0;" ::: "memory");
        __syncthreads();   // sync2
    }

    // ---- epilogue: O/l + residual ----
#pragma unroll
    for (int mt = 0; mt < 4; mt++) {
        int r0 = mw * 64 + mt * 16 + g;
        float inv0 = 1.0f / sL[r0];
        float inv1 = 1.0f / sL[r0 + 8];
        size_t row0 = (size_t)b * SEQ + q0 + r0;
#pragma unroll
        for (int nt = 0; nt < 8; nt++) {
            int col = nw * 64 + nt * 8 + l4 * 2;
            const float2* x0 = (const float2*)(X + (row0)*CDIM + col);
            const float2* x1 = (const float2*)(X + (row0 + 8) * CDIM + col);
            float2 xv0 = *x0, xv1 = *x1;
            float2 o0, o1;
            o0.x = oa[mt][nt][0] * inv0 + xv0.x;
            o0.y = oa[mt][nt][1] * inv0 + xv0.y;
            o1.x = oa[mt][nt][2] * inv1 + xv1.x;
            o1.y = oa[mt][nt][3] * inv1 + xv1.y;
            *(float2*)(Out + (row0)*CDIM + col) = o0;
            *(float2*)(Out + (row0 + 8) * CDIM + col) = o1;
        }
    }
}

// ============================================================================
// Merged projections: blocks [0,256) = V tf32-mma GEMM tiles,
//                     blocks [256,512) = q/k FFMA2 tiles (k in bf16 KT layout).
// 256 threads, 64 KB dynamic smem.
// ============================================================================
#define PROJ_SMEM 65536
__device__ __forceinline__ int pA8(int r, int k) { return r * 32 + (k ^ ((r & 7) * 4)); }
__device__ __forceinline__ int pB8(int k, int n) { return k * 128 + (n ^ ((k & 3) * 8)); }

__global__ __launch_bounds__(256)
void proj_all(const float* __restrict__ Xg,
              const float* __restrict__ Wq, const float* __restrict__ bq,
              const float* __restrict__ Wk, const float* __restrict__ bk,
              const float* __restrict__ Wv, const float* __restrict__ bv,
              float* __restrict__ Yq, float* __restrict__ KTH, float* __restrict__ KTL,
              float* __restrict__ Vout) {
    extern __shared__ char smem[];
    const int tid  = threadIdx.x;

    if (blockIdx.x < 256) {
        // ---------------- V projection (tf32 mma) ----------------
        float* sA = (float*)smem;
        float* sB = (float*)(smem + 32768);
        const uint32_t sb = smem_u32(smem);
        const int lane = tid & 31;
        const int wid  = tid >> 5;
        const int mw   = wid & 1;
        const int nw   = wid >> 1;
        const int g    = lane >> 2;
        const int l4   = lane & 3;
        const int m0   = (blockIdx.x >> 1) * 128;
        const int n0   = (blockIdx.x & 1) * 128;

        float acc[4][4][4];
#pragma unroll
        for (int mt = 0; mt < 4; mt++)
#pragma unroll
            for (int nt = 0; nt < 4; nt++)
#pragma unroll
                for (int c = 0; c < 4; c++) acc[mt][nt][c] = 0.0f;

        auto load_tiles = [&](int k0, int bufsel) {
            uint32_t abase = sb + (uint32_t)bufsel * 16384u;
            uint32_t bbase = sb + 32768u + (uint32_t)bufsel * 16384u;
#pragma unroll
            for (int i = 0; i < 4; i++) {
                int idx = tid + i * 256;
                int r = idx >> 3, c4 = idx & 7;
                uint32_t dst = abase + (uint32_t)(r * 32 + ((c4 * 4) ^ ((r & 7) * 4))) * 4u;
                cp_async16(dst, Xg + (size_t)(m0 + r) * CDIM + k0 + c4 * 4);
            }
#pragma unroll
            for (int i = 0; i < 4; i++) {
                int idx = tid + i * 256;
                int k = idx >> 5, n4 = idx & 31;
                uint32_t dst = bbase + (uint32_t)(k * 128 + ((n4 * 4) ^ ((k & 3) * 8))) * 4u;
                cp_async16(dst, Wv + (size_t)(k0 + k) * CDIM + n0 + n4 * 4);
            }
            asm volatile("cp.async.commit_group;" ::: "memory");
        };

        load_tiles(0, 0);

#pragma unroll 1
        for (int t = 0; t < 8; t++) {
            const int buf = t & 1;
            const bool have_next = (t + 1 < 8);
            if (have_next) load_tiles((t + 1) * 32, 1 - buf);
            if (have_next) asm volatile("cp.async.wait_group 1;" ::: "memory");
            else           asm volatile("cp.async.wait_group 0;" ::: "memory");
            __syncthreads();

            const float* A = sA + (size_t)buf * 4096;
            const float* B = sB + (size_t)buf * 4096;
#pragma unroll
            for (int ks = 0; ks < 4; ks++) {
                const int k8 = ks * 8;
                uint32_t bfr[4][2];
#pragma unroll
                for (int nt = 0; nt < 4; nt++) {
                    int n = nw * 32 + nt * 8 + g;
                    bfr[nt][0] = __float_as_uint(B[pB8(k8 + l4, n)]);
                    bfr[nt][1] = __float_as_uint(B[pB8(k8 + 4 + l4, n)]);
                }
#pragma unroll
                for (int mt = 0; mt < 4; mt++) {
                    int r0 = mw * 64 + mt * 16 + g;
                    uint32_t a0 = __float_as_uint(A[pA8(r0, k8 + l4)]);
                    uint32_t a1 = __float_as_uint(A[pA8(r0 + 8, k8 + l4)]);
                    uint32_t a2 = __float_as_uint(A[pA8(r0, k8 + 4 + l4)]);
                    uint32_t a3 = __float_as_uint(A[pA8(r0 + 8, k8 + 4 + l4)]);
#pragma unroll
                    for (int nt = 0; nt < 4; nt++)
                        mma8(acc[mt][nt], a0, a1, a2, a3, bfr[nt][0], bfr[nt][1]);
                }
            }
            __syncthreads();
        }

#pragma unroll
        for (int mt = 0; mt < 4; mt++) {
            int r0 = m0 + mw * 64 + mt * 16 + g;
#pragma unroll
            for (int nt = 0; nt < 4; nt++) {
                int col = n0 + nw * 32 + nt * 8 + l4 * 2;
                float2 bb = *(const float2*)(bv + col);
                float2 o0, o1;
                o0.x = acc[mt][nt][0] + bb.x;
                o0.y = acc[mt][nt][1] + bb.y;
                o1.x = acc[mt][nt][2] + bb.x;
                o1.y = acc[mt][nt][3] + bb.y;
                *(float2*)(Vout + (size_t)r0 * CDIM + col) = o0;
                *(float2*)(Vout + (size_t)(r0 + 8) * CDIM + col) = o1;
            }
        }
    } else {
        // ---------------- q/k projection (FFMA2), k -> bf16 KT layout ----------------
        constexpr int BK = 16, TM = 2, TN = 4, TX = 8;
        float* As = (float*)smem;              // [16][68]
        float* Bq = As + 16 * 68;              // [16][32]
        float* Bk = Bq + 16 * 32;              // [16][32]
        const int tx = tid % TX, ty = tid / TX;
        const int m0 = (blockIdx.x - 256) * 64;

        unsigned long long aq[TM][2], ak[TM][2];
#pragma unroll
        for (int i = 0; i < TM; i++) {
            aq[i][0] = aq[i][1] = 0ull;
            ak[i][0] = ak[i][1] = 0ull;
        }

        for (int k0 = 0; k0 < CDIM; k0 += BK) {
            {
                int m = tid >> 2, kq = tid & 3;
                float4 t4 = *(const float4*)(Xg + (size_t)(m0 + m) * CDIM + k0 + kq * 4);
                As[(kq * 4 + 0) * 68 + m] = t4.x; As[(kq * 4 + 1) * 68 + m] = t4.y;
                As[(kq * 4 + 2) * 68 + m] = t4.z; As[(kq * 4 + 3) * 68 + m] = t4.w;
            }
            if (tid < 128) {
                int kk = tid >> 3, nq = tid & 7;
                *(float4*)&Bq[kk * 32 + nq * 4] = *(const float4*)(Wq + (size_t)(k0 + kk) * DDIM + nq * 4);
                *(float4*)&Bk[kk * 32 + nq * 4] = *(const float4*)(Wk + (size_t)(k0 + kk) * DDIM + nq * 4);
            }
            __syncthreads();
#pragma unroll
            for (int kk = 0; kk < BK; kk++) {
                ulonglong2 bbq = *(const ulonglong2*)&Bq[kk * 32 + tx * TN];
                ulonglong2 bbk = *(const ulonglong2*)&Bk[kk * 32 + tx * TN];
#pragma unroll
                for (int i = 0; i < TM; i++) {
                    float a = As[kk * 68 + ty * TM + i];
                    unsigned long long a2 = pack2(a, a);
                    aq[i][0] = ffma2(bbq.x, a2, aq[i][0]);
                    aq[i][1] = ffma2(bbq.y, a2, aq[i][1]);
                    ak[i][0] = ffma2(bbk.x, a2, ak[i][0]);
                    ak[i][1] = ffma2(bbk.y, a2, ak[i][1]);
                }
            }
            __syncthreads();
        }
        float4 bq4 = *(const float4*)(bq + tx * TN);
        float4 bk4 = *(const float4*)(bk + tx * TN);
#pragma unroll
        for (int i = 0; i < TM; i++) {
            int m = m0 + ty * TM + i;
            float v0, v1, v2, v3;
            unpack2(aq[i][0], v0, v1);
            unpack2(aq[i][1], v2, v3);
            float4 o;
            o.x = v0 + bq4.x; o.y = v1 + bq4.y; o.z = v2 + bq4.z; o.w = v3 + bq4.w;
            *(float4*)(Yq + (size_t)m * DDIM + tx * TN) = o;
            // k: bf16 hi/lo split, packed pairs into KT tile layout
            float kv[4];
            unpack2(ak[i][0], kv[0], kv[1]);
            unpack2(ak[i][1], kv[2], kv[3]);
            kv[0] += bk4.x; kv[1] += bk4.y; kv[2] += bk4.z; kv[3] += bk4.w;
            int key = m & 63;
            size_t base = (size_t)(m >> 6) * 1024;
            uint32_t hi0 = bftruncpack(kv[0], kv[1]);
            uint32_t hi1 = bftruncpack(kv[2], kv[3]);
            uint32_t lo0 = bfpack(bftrunc_res(kv[0]), bftrunc_res(kv[1]));
            uint32_t lo1 = bfpack(bftrunc_res(kv[2]), bftrunc_res(kv[3]));
            int w0 = pK16(key, 2 * tx);
            int w1 = pK16(key, 2 * tx + 1);
            ((uint32_t*)KTH)[base + w0] = hi0;
            ((uint32_t*)KTH)[base + w1] = hi1;
            ((uint32_t*)KTL)[base + w0] = lo0;
            ((uint32_t*)KTL)[base + w1] = lo1;
        }
    }
}

// ============================================================================
extern "C" void kernel_launch(void* const* d_in, const int* in_sizes, int n_in,
                              void* d_out, int out_size) {
    const float* x  = (const float*)d_in[0];
    const float* wq = (const float*)d_in[1];
    const float* bq = (const float*)d_in[2];
    const float* wk = (const float*)d_in[3];
    const float* bk = (const float*)d_in[4];
    const float* wv = (const float*)d_in[5];
    const float* bv = (const float*)d_in[6];
    float* out = (float*)d_out;

    float *qp, *kthp, *ktlp, *vp;
    cudaGetSymbolAddress((void**)&qp, g_q);
    cudaGetSymbolAddress((void**)&kthp, g_kth);
    cudaGetSymbolAddress((void**)&ktlp, g_ktl);
    cudaGetSymbolAddress((void**)&vp, g_v);

    {
        cudaFuncSetAttribute(proj_all, cudaFuncAttributeMaxDynamicSharedMemorySize, PROJ_SMEM);
        proj_all<<<512, 256, PROJ_SMEM>>>(x, wq, bq, wk, bk, wv, bv, qp, kthp, ktlp, vp);
    }
    {
        cudaFuncSetAttribute(flash_mma, cudaFuncAttributeMaxDynamicSharedMemorySize, FLASH_SMEM);
        dim3 g(SEQ / TQ, BATCH);
        flash_mma<<<g, 256, FLASH_SMEM>>>(qp, kthp, ktlp, vp, x, out);
    }
}